// round 3
// baseline (speedup 1.0000x reference)
#include <cuda_runtime.h>
#include <math.h>

// ---------------------------------------------------------------------------
// Problem constants
// ---------------------------------------------------------------------------
#define BATCH   4
#define SEQ     2048
#define DMODEL  2048
#define NHEAD   16
#define HDIM    128           // DMODEL / NHEAD
#define BT      (BATCH * SEQ) // 8192 rows

// ---------------------------------------------------------------------------
// Scratch buffers (allocation-free rule: __device__ globals)
// ---------------------------------------------------------------------------
__device__ float g_q[(size_t)BT * DMODEL];
__device__ float g_k[(size_t)BT * DMODEL];
__device__ float g_v[(size_t)BT * DMODEL];
__device__ float g_o[(size_t)BT * DMODEL];
__device__ float2 g_rope_tab[SEQ * 64];   // (cos, sin) per (t, pair-index)

// ---------------------------------------------------------------------------
// RoPE table: computed in DOUBLE precision so --use_fast_math cannot degrade
// the trig (single-precision __sincosf has no argument reduction; angles reach
// ~2047 rad). Angle itself is formed via f32 rounding to mimic the reference.
// ---------------------------------------------------------------------------
__global__ __launch_bounds__(256)
void rope_table_kernel() {
    int idx = blockIdx.x * blockDim.x + threadIdx.x;
    if (idx >= SEQ * 64) return;
    int i = idx & 63;        // pair index
    int t = idx >> 6;        // position
    // inv_freq = 10000^(-i/64), computed exactly in double, rounded to f32
    float inv_freq = (float)exp(-log(10000.0) * ((double)i / 64.0));
    float ang_f = (float)t * inv_freq;          // f32 rounding (matches jnp)
    double ang = (double)ang_f;
    g_rope_tab[idx] = make_float2((float)cos(ang), (float)sin(ang));
}

// ---------------------------------------------------------------------------
// SGEMM: C[M,N] = A[M,K] * B[N,K]^T   (all row-major, K contiguous)
// 128x128 block tile, BK=16, 256 threads, 8x8 per thread.
// ---------------------------------------------------------------------------
#define GBM 128
#define GBN 128
#define GBK 16

__global__ __launch_bounds__(256)
void sgemm_abT(const float* __restrict__ A, const float* __restrict__ B,
               float* __restrict__ C, int M, int N, int K) {
    __shared__ float As[GBK][GBM + 4];
    __shared__ float Bs[GBK][GBN + 4];

    const int bx = blockIdx.x;   // N tile
    const int by = blockIdx.y;   // M tile
    const int tid = threadIdx.x;
    const int tx = tid & 15;
    const int ty = tid >> 4;

    const float* Aptr = A + (size_t)by * GBM * K;
    const float* Bptr = B + (size_t)bx * GBN * K;

    float acc[8][8];
#pragma unroll
    for (int i = 0; i < 8; i++)
#pragma unroll
        for (int j = 0; j < 8; j++) acc[i][j] = 0.f;

    for (int k0 = 0; k0 < K; k0 += GBK) {
#pragma unroll
        for (int l = 0; l < 2; l++) {
            int idx = tid + l * 256;          // 0..511
            int row = idx >> 2;               // 0..127
            int c4  = (idx & 3) * 4;          // 0,4,8,12
            float4 va = *(const float4*)(Aptr + (size_t)row * K + k0 + c4);
            As[c4 + 0][row] = va.x;
            As[c4 + 1][row] = va.y;
            As[c4 + 2][row] = va.z;
            As[c4 + 3][row] = va.w;
            float4 vb = *(const float4*)(Bptr + (size_t)row * K + k0 + c4);
            Bs[c4 + 0][row] = vb.x;
            Bs[c4 + 1][row] = vb.y;
            Bs[c4 + 2][row] = vb.z;
            Bs[c4 + 3][row] = vb.w;
        }
        __syncthreads();

#pragma unroll
        for (int kk = 0; kk < GBK; kk++) {
            float4 a0 = *(const float4*)&As[kk][ty * 8];
            float4 a1 = *(const float4*)&As[kk][ty * 8 + 4];
            float4 b0 = *(const float4*)&Bs[kk][tx * 8];
            float4 b1 = *(const float4*)&Bs[kk][tx * 8 + 4];
            float a[8] = {a0.x, a0.y, a0.z, a0.w, a1.x, a1.y, a1.z, a1.w};
            float b[8] = {b0.x, b0.y, b0.z, b0.w, b1.x, b1.y, b1.z, b1.w};
#pragma unroll
            for (int i = 0; i < 8; i++)
#pragma unroll
                for (int j = 0; j < 8; j++)
                    acc[i][j] = fmaf(a[i], b[j], acc[i][j]);
        }
        __syncthreads();
    }

#pragma unroll
    for (int i = 0; i < 8; i++) {
        float* crow = C + (size_t)(by * GBM + ty * 8 + i) * N + bx * GBN + tx * 8;
        float4 c0 = make_float4(acc[i][0], acc[i][1], acc[i][2], acc[i][3]);
        float4 c1 = make_float4(acc[i][4], acc[i][5], acc[i][6], acc[i][7]);
        *(float4*)(crow)     = c0;
        *(float4*)(crow + 4) = c1;
    }
}

// ---------------------------------------------------------------------------
// RoPE applied in-place to q and k, reading the precomputed table.
// Layout: (B*T, H*HDIM); pos = t = bt % SEQ.
// out[i]     = x1*cos - x2*sin
// out[i+64]  = x2*cos + x1*sin
// ---------------------------------------------------------------------------
__global__ __launch_bounds__(256)
void rope_kernel(float* __restrict__ q, float* __restrict__ k) {
    const size_t total = (size_t)BT * NHEAD * (HDIM / 2); // 8.4M
    size_t idx = (size_t)blockIdx.x * blockDim.x + threadIdx.x;
    if (idx >= total) return;

    int i  = (int)(idx & 63);                  // pair index 0..63
    int h  = (int)((idx >> 6) & (NHEAD - 1));  // head
    int bt = (int)(idx >> 10);                 // row
    int t  = bt & (SEQ - 1);

    float2 cs = g_rope_tab[t * 64 + i];
    float c = cs.x, s = cs.y;

    size_t base = (size_t)bt * DMODEL + h * HDIM + i;

    float q1 = q[base], q2 = q[base + 64];
    q[base]      = q1 * c - q2 * s;
    q[base + 64] = q2 * c + q1 * s;

    float k1 = k[base], k2 = k[base + 64];
    k[base]      = k1 * c - k2 * s;
    k[base + 64] = k2 * c + k1 * s;
}

// ---------------------------------------------------------------------------
// Flash attention (causal, fp32, online softmax).
// Grid: (SEQ/64, B*H). Block: 256 threads (16x16 logical grid).
// ---------------------------------------------------------------------------
#define FBM 64
#define FBN 64
#define QSTR 132   // HDIM + 4 pad
#define PSTR 68    // FBN + 4 pad

#define FSMEM_FLOATS (3 * 64 * QSTR + 64 * PSTR)
#define FSMEM_BYTES  (FSMEM_FLOATS * 4)

__global__ __launch_bounds__(256)
void flash_attn(const float* __restrict__ q, const float* __restrict__ k,
                const float* __restrict__ v, float* __restrict__ o) {
    extern __shared__ float fs[];
    float* Qs = fs;                    // 64 x 132
    float* Ks = Qs + 64 * QSTR;        // 64 x 132
    float* Vs = Ks + 64 * QSTR;        // 64 x 132
    float* Ps = Vs + 64 * QSTR;        // 64 x 68

    const int mb = blockIdx.x;         // query tile
    const int bh = blockIdx.y;
    const int b  = bh / NHEAD;
    const int h  = bh % NHEAD;
    const int tid = threadIdx.x;
    const int tx = tid & 15;
    const int ty = tid >> 4;
    const float scale = 0.08838834764831845f;  // 1/sqrt(128)

    const float* qbase = q + (size_t)b * SEQ * DMODEL + h * HDIM;
    const float* kbase = k + (size_t)b * SEQ * DMODEL + h * HDIM;
    const float* vbase = v + (size_t)b * SEQ * DMODEL + h * HDIM;

    for (int l = tid; l < 64 * 32; l += 256) {
        int r  = l >> 5;
        int c4 = (l & 31) * 4;
        float4 t4 = *(const float4*)(qbase + (size_t)(mb * FBM + r) * DMODEL + c4);
        Qs[r * QSTR + c4 + 0] = t4.x;
        Qs[r * QSTR + c4 + 1] = t4.y;
        Qs[r * QSTR + c4 + 2] = t4.z;
        Qs[r * QSTR + c4 + 3] = t4.w;
    }

    float m_i[4], l_i[4], Oacc[4][8];
#pragma unroll
    for (int i = 0; i < 4; i++) {
        m_i[i] = -INFINITY;
        l_i[i] = 0.f;
#pragma unroll
        for (int jj = 0; jj < 8; jj++) Oacc[i][jj] = 0.f;
    }
    __syncthreads();

    for (int jb = 0; jb <= mb; jb++) {
        for (int l = tid; l < 64 * 32; l += 256) {
            int r  = l >> 5;
            int c4 = (l & 31) * 4;
            size_t goff = (size_t)(jb * FBN + r) * DMODEL + c4;
            float4 kt = *(const float4*)(kbase + goff);
            Ks[r * QSTR + c4 + 0] = kt.x;
            Ks[r * QSTR + c4 + 1] = kt.y;
            Ks[r * QSTR + c4 + 2] = kt.z;
            Ks[r * QSTR + c4 + 3] = kt.w;
            float4 vt = *(const float4*)(vbase + goff);
            Vs[r * QSTR + c4 + 0] = vt.x;
            Vs[r * QSTR + c4 + 1] = vt.y;
            Vs[r * QSTR + c4 + 2] = vt.z;
            Vs[r * QSTR + c4 + 3] = vt.w;
        }
        __syncthreads();

        float s[4][4];
#pragma unroll
        for (int i = 0; i < 4; i++)
#pragma unroll
            for (int j = 0; j < 4; j++) s[i][j] = 0.f;

        for (int kk = 0; kk < HDIM; kk += 4) {
            float4 a4[4], b4[4];
#pragma unroll
            for (int i = 0; i < 4; i++)
                a4[i] = *(const float4*)&Qs[(ty * 4 + i) * QSTR + kk];
#pragma unroll
            for (int j = 0; j < 4; j++)
                b4[j] = *(const float4*)&Ks[(tx * 4 + j) * QSTR + kk];
#pragma unroll
            for (int i = 0; i < 4; i++)
#pragma unroll
                for (int j = 0; j < 4; j++) {
                    s[i][j] = fmaf(a4[i].x, b4[j].x, s[i][j]);
                    s[i][j] = fmaf(a4[i].y, b4[j].y, s[i][j]);
                    s[i][j] = fmaf(a4[i].z, b4[j].z, s[i][j]);
                    s[i][j] = fmaf(a4[i].w, b4[j].w, s[i][j]);
                }
        }

#pragma unroll
        for (int i = 0; i < 4; i++)
#pragma unroll
            for (int j = 0; j < 4; j++) {
                s[i][j] *= scale;
                if (jb == mb && (tx * 4 + j) > (ty * 4 + i)) s[i][j] = -INFINITY;
            }

#pragma unroll
        for (int i = 0; i < 4; i++) {
            float mn = fmaxf(fmaxf(s[i][0], s[i][1]), fmaxf(s[i][2], s[i][3]));
#pragma unroll
            for (int off = 1; off < 16; off <<= 1)
                mn = fmaxf(mn, __shfl_xor_sync(0xffffffffu, mn, off));
            mn = fmaxf(mn, m_i[i]);

            float alpha = __expf(m_i[i] - mn);
            m_i[i] = mn;
            l_i[i] *= alpha;
#pragma unroll
            for (int jj = 0; jj < 8; jj++) Oacc[i][jj] *= alpha;

            float rs = 0.f;
#pragma unroll
            for (int j = 0; j < 4; j++) {
                float p = __expf(s[i][j] - mn);
                s[i][j] = p;
                rs += p;
            }
#pragma unroll
            for (int off = 1; off < 16; off <<= 1)
                rs += __shfl_xor_sync(0xffffffffu, rs, off);
            l_i[i] += rs;
        }

#pragma unroll
        for (int i = 0; i < 4; i++) {
            float4 p4 = make_float4(s[i][0], s[i][1], s[i][2], s[i][3]);
            *(float4*)&Ps[(ty * 4 + i) * PSTR + tx * 4] = p4;
        }
        __syncthreads();

        for (int kk = 0; kk < FBN; kk++) {
            float a[4];
#pragma unroll
            for (int i = 0; i < 4; i++) a[i] = Ps[(ty * 4 + i) * PSTR + kk];
            float4 vb0 = *(const float4*)&Vs[kk * QSTR + tx * 8];
            float4 vb1 = *(const float4*)&Vs[kk * QSTR + tx * 8 + 4];
            float bb[8] = {vb0.x, vb0.y, vb0.z, vb0.w, vb1.x, vb1.y, vb1.z, vb1.w};
#pragma unroll
            for (int i = 0; i < 4; i++)
#pragma unroll
                for (int jj = 0; jj < 8; jj++)
                    Oacc[i][jj] = fmaf(a[i], bb[jj], Oacc[i][jj]);
        }
        __syncthreads();
    }

    float* obase = o + (size_t)b * SEQ * DMODEL + h * HDIM;
#pragma unroll
    for (int i = 0; i < 4; i++) {
        float inv_l = 1.0f / l_i[i];
        float* orow = obase + (size_t)(mb * FBM + ty * 4 + i) * DMODEL + tx * 8;
        float4 o0 = make_float4(Oacc[i][0] * inv_l, Oacc[i][1] * inv_l,
                                Oacc[i][2] * inv_l, Oacc[i][3] * inv_l);
        float4 o1 = make_float4(Oacc[i][4] * inv_l, Oacc[i][5] * inv_l,
                                Oacc[i][6] * inv_l, Oacc[i][7] * inv_l);
        *(float4*)(orow)     = o0;
        *(float4*)(orow + 4) = o1;
    }
}

// ---------------------------------------------------------------------------
// Launch
// ---------------------------------------------------------------------------
extern "C" void kernel_launch(void* const* d_in, const int* in_sizes, int n_in,
                              void* d_out, int out_size) {
    const float* x  = (const float*)d_in[0];
    const float* wq = (const float*)d_in[1];
    const float* wk = (const float*)d_in[2];
    const float* wv = (const float*)d_in[3];
    const float* wo = (const float*)d_in[4];
    float* out = (float*)d_out;

    float *qp, *kp, *vp, *op;
    cudaGetSymbolAddress((void**)&qp, g_q);
    cudaGetSymbolAddress((void**)&kp, g_k);
    cudaGetSymbolAddress((void**)&vp, g_v);
    cudaGetSymbolAddress((void**)&op, g_o);

    dim3 gemm_grid(DMODEL / GBN, BT / GBM);   // (16, 64)

    // RoPE table (double-precision trig, immune to fast-math)
    rope_table_kernel<<<(SEQ * 64 + 255) / 256, 256>>>();

    // QKV projections
    sgemm_abT<<<gemm_grid, 256>>>(x, wq, qp, BT, DMODEL, DMODEL);
    sgemm_abT<<<gemm_grid, 256>>>(x, wk, kp, BT, DMODEL, DMODEL);
    sgemm_abT<<<gemm_grid, 256>>>(x, wv, vp, BT, DMODEL, DMODEL);

    // RoPE on q,k
    {
        size_t total = (size_t)BT * NHEAD * (HDIM / 2);
        int blocks = (int)((total + 255) / 256);
        rope_kernel<<<blocks, 256>>>(qp, kp);
    }

    // Flash attention
    cudaFuncSetAttribute(flash_attn, cudaFuncAttributeMaxDynamicSharedMemorySize,
                         FSMEM_BYTES);
    flash_attn<<<dim3(SEQ / FBM, BATCH * NHEAD), 256, FSMEM_BYTES>>>(qp, kp, vp, op);

    // Output projection
    sgemm_abT<<<gemm_grid, 256>>>(op, wo, out, BT, DMODEL, DMODEL);
}

// round 6
// speedup vs baseline: 1.4929x; 1.4929x over previous
#include <cuda_runtime.h>
#include <cuda_bf16.h>
#include <math.h>
#include <stdint.h>

// ---------------------------------------------------------------------------
// Problem constants
// ---------------------------------------------------------------------------
#define BATCH   4
#define SEQ     2048
#define DMODEL  2048
#define NHEAD   16
#define HDIM    128
#define BT      (BATCH * SEQ)   // 8192

__device__ __forceinline__ uint32_t smem_to_u32(const void* smem_ptr) {
    uint32_t addr;
    asm("{ .reg .u64 tmp; cvta.to.shared.u64 tmp, %1; cvt.u32.u64 %0, tmp; }"
        : "=r"(addr) : "l"(smem_ptr));
    return addr;
}

#define CP_ASYNC_16(dst_u32, src_ptr) \
    asm volatile("cp.async.cg.shared.global [%0], [%1], 16;" \
        :: "r"(dst_u32), "l"(src_ptr) : "memory")
#define CP_ASYNC_COMMIT() asm volatile("cp.async.commit_group;" ::: "memory")
#define CP_ASYNC_WAIT_1() asm volatile("cp.async.wait_group 1;" ::: "memory")

#define LDMATRIX_X4(r0, r1, r2, r3, addr) \
    asm volatile("ldmatrix.sync.aligned.m8n8.x4.shared.b16 {%0,%1,%2,%3}, [%4];" \
        : "=r"(r0), "=r"(r1), "=r"(r2), "=r"(r3) : "r"(addr))

#define MMA_BF16(c, a, b) \
    asm volatile( \
        "mma.sync.aligned.m16n8k16.row.col.f32.bf16.bf16.f32 " \
        "{%0,%1,%2,%3}, {%4,%5,%6,%7}, {%8,%9}, {%0,%1,%2,%3};" \
        : "+f"((c)[0]), "+f"((c)[1]), "+f"((c)[2]), "+f"((c)[3]) \
        : "r"((a)[0]), "r"((a)[1]), "r"((a)[2]), "r"((a)[3]), \
          "r"((b)[0]), "r"((b)[1]))

// ---------------------------------------------------------------------------
// Scratch (allocation-free rule: __device__ globals)
// ---------------------------------------------------------------------------
__device__ float g_q[(size_t)BT * DMODEL];
__device__ float g_k[(size_t)BT * DMODEL];
__device__ float g_v[(size_t)BT * DMODEL];
__device__ float g_o[(size_t)BT * DMODEL];
__device__ float2 g_rope_tab[SEQ * 64];

__device__ __nv_bfloat16 g_xhi[(size_t)BT * DMODEL];
__device__ __nv_bfloat16 g_xlo[(size_t)BT * DMODEL];
__device__ __nv_bfloat16 g_ohi[(size_t)BT * DMODEL];
__device__ __nv_bfloat16 g_olo[(size_t)BT * DMODEL];
__device__ __nv_bfloat16 g_wqhi[(size_t)DMODEL * DMODEL];
__device__ __nv_bfloat16 g_wqlo[(size_t)DMODEL * DMODEL];
__device__ __nv_bfloat16 g_wkhi[(size_t)DMODEL * DMODEL];
__device__ __nv_bfloat16 g_wklo[(size_t)DMODEL * DMODEL];
__device__ __nv_bfloat16 g_wvhi[(size_t)DMODEL * DMODEL];
__device__ __nv_bfloat16 g_wvlo[(size_t)DMODEL * DMODEL];
__device__ __nv_bfloat16 g_wohi[(size_t)DMODEL * DMODEL];
__device__ __nv_bfloat16 g_wolo[(size_t)DMODEL * DMODEL];

// ---------------------------------------------------------------------------
// fp32 -> (bf16 hi, bf16 lo) split
// ---------------------------------------------------------------------------
__global__ __launch_bounds__(256)
void split_bf16(const float* __restrict__ src,
                __nv_bfloat16* __restrict__ hi, __nv_bfloat16* __restrict__ lo,
                size_t n) {
    size_t i = (size_t)blockIdx.x * blockDim.x + threadIdx.x;
    if (i >= n) return;
    float x = src[i];
    __nv_bfloat16 h = __float2bfloat16(x);
    float r = x - __bfloat162float(h);
    hi[i] = h;
    lo[i] = __float2bfloat16(r);
}

// ---------------------------------------------------------------------------
// RoPE table in double precision (immune to --use_fast_math)
// ---------------------------------------------------------------------------
__global__ __launch_bounds__(256)
void rope_table_kernel() {
    int idx = blockIdx.x * blockDim.x + threadIdx.x;
    if (idx >= SEQ * 64) return;
    int i = idx & 63;
    int t = idx >> 6;
    float inv_freq = (float)exp(-log(10000.0) * ((double)i / 64.0));
    float ang_f = (float)t * inv_freq;
    double ang = (double)ang_f;
    g_rope_tab[idx] = make_float2((float)cos(ang), (float)sin(ang));
}

// ---------------------------------------------------------------------------
// bf16-split GEMM on mma.sync:  C[M,N] = (Ahi+Alo)[M,K] * (Bhi+Blo)[N,K]^T
//   Block tile 128x128, BK=32, 256 threads (2x4 warps, 64x32 warp tile).
//   3 passes per k-step: hi*hi + hi*lo + lo*hi into f32 accum.
//   cp.async double buffer; smem rows padded to 80B (conflict-free ldmatrix).
// ---------------------------------------------------------------------------
#define BM 128
#define BN 128
#define BK 32
#define ROWB 80                       // bytes per smem row (32 bf16 = 64B + pad)
#define TILE_B (128 * ROWB)           // 10240 B per tile
#define STAGE_B (4 * TILE_B)          // Ahi,Alo,Bhi,Blo = 40960 B
#define GEMM_SMEM (2 * STAGE_B)       // 81920 B

__global__ __launch_bounds__(256, 1)
void gemm_bf16split(const __nv_bfloat16* __restrict__ Ahi,
                    const __nv_bfloat16* __restrict__ Alo,
                    const __nv_bfloat16* __restrict__ Bhi,
                    const __nv_bfloat16* __restrict__ Blo,
                    float* __restrict__ C, int M, int N, int K) {
    extern __shared__ char smem[];
    const uint32_t sb = smem_to_u32(smem);
    const int tid  = threadIdx.x;
    const int lane = tid & 31;
    const int wid  = tid >> 5;
    const int warp_m = wid & 1;     // 0..1  (64-row slabs)
    const int warp_n = wid >> 1;    // 0..3  (32-col slabs)

    const int row0 = blockIdx.y * BM;
    const int col0 = blockIdx.x * BN;

    float acc[4][4][4];
#pragma unroll
    for (int mi = 0; mi < 4; mi++)
#pragma unroll
        for (int ni = 0; ni < 4; ni++)
#pragma unroll
            for (int e = 0; e < 4; e++) acc[mi][ni][e] = 0.f;

    const int r_ld  = tid >> 2;          // 0..63  (two rows per thread via +64)
    const int c_ld  = (tid & 3) * 16;    // byte chunk within row
    const int ke_ld = (tid & 3) * 8;     // element offset

    // ---- prologue: stage 0 ----
    {
        const int k0 = 0;
#pragma unroll
        for (int half = 0; half < 2; half++) {
            int r = r_ld + half * 64;
            uint32_t d = sb + r * ROWB + c_ld;
            size_t ga = (size_t)(row0 + r) * K + k0 + ke_ld;
            size_t gb = (size_t)(col0 + r) * K + k0 + ke_ld;
            CP_ASYNC_16(d + 0 * TILE_B, Ahi + ga);
            CP_ASYNC_16(d + 1 * TILE_B, Alo + ga);
            CP_ASYNC_16(d + 2 * TILE_B, Bhi + gb);
            CP_ASYNC_16(d + 3 * TILE_B, Blo + gb);
        }
        CP_ASYNC_COMMIT();
    }

    const int niter = K / BK;
    for (int kt = 0; kt < niter; kt++) {
        // ---- prefetch next stage ----
        if (kt + 1 < niter) {
            const int k0 = (kt + 1) * BK;
            const uint32_t base = sb + ((kt + 1) & 1) * STAGE_B;
#pragma unroll
            for (int half = 0; half < 2; half++) {
                int r = r_ld + half * 64;
                uint32_t d = base + r * ROWB + c_ld;
                size_t ga = (size_t)(row0 + r) * K + k0 + ke_ld;
                size_t gb = (size_t)(col0 + r) * K + k0 + ke_ld;
                CP_ASYNC_16(d + 0 * TILE_B, Ahi + ga);
                CP_ASYNC_16(d + 1 * TILE_B, Alo + ga);
                CP_ASYNC_16(d + 2 * TILE_B, Bhi + gb);
                CP_ASYNC_16(d + 3 * TILE_B, Blo + gb);
            }
        }
        CP_ASYNC_COMMIT();
        CP_ASYNC_WAIT_1();      // current stage resident
        __syncthreads();

        const uint32_t base  = sb + (kt & 1) * STAGE_B;
        const uint32_t a_hiB = base + 0 * TILE_B;
        const uint32_t a_loB = base + 1 * TILE_B;
        const uint32_t b_hiB = base + 2 * TILE_B;
        const uint32_t b_loB = base + 3 * TILE_B;

#pragma unroll
        for (int ks = 0; ks < 2; ks++) {            // two k16 steps per BK
            const int kb = ks * 32;                  // byte offset of k-step

            uint32_t ah[4][4], al[4][4], bh[4][2], bl[4][2];
            // A fragments (m16k16 each): lanes 0-15 rows, 16-31 rows at k+8
            const int ar = warp_m * 64 + (lane & 15);
            const uint32_t acol = kb + ((lane >> 4) << 4);
#pragma unroll
            for (int mi = 0; mi < 4; mi++) {
                uint32_t off = (uint32_t)(ar + mi * 16) * ROWB + acol;
                LDMATRIX_X4(ah[mi][0], ah[mi][1], ah[mi][2], ah[mi][3], a_hiB + off);
                LDMATRIX_X4(al[mi][0], al[mi][1], al[mi][2], al[mi][3], a_loB + off);
            }
            // B fragments: x4 covers two n8 frags (n16 x k16)
            const int brr = warp_n * 32 + ((lane >> 4) & 1) * 8 + (lane & 7);
            const uint32_t bcol = kb + ((lane >> 3) & 1) * 16;
#pragma unroll
            for (int nb = 0; nb < 2; nb++) {
                uint32_t off = (uint32_t)(brr + nb * 16) * ROWB + bcol;
                LDMATRIX_X4(bh[2*nb][0], bh[2*nb][1], bh[2*nb+1][0], bh[2*nb+1][1],
                            b_hiB + off);
                LDMATRIX_X4(bl[2*nb][0], bl[2*nb][1], bl[2*nb+1][0], bl[2*nb+1][1],
                            b_loB + off);
            }
#pragma unroll
            for (int mi = 0; mi < 4; mi++)
#pragma unroll
                for (int ni = 0; ni < 4; ni++) {
                    MMA_BF16(acc[mi][ni], ah[mi], bh[ni]);
                    MMA_BF16(acc[mi][ni], ah[mi], bl[ni]);
                    MMA_BF16(acc[mi][ni], al[mi], bh[ni]);
                }
        }
        __syncthreads();   // all warps done with this stage before it is reloaded
    }

    // ---- epilogue ----
#pragma unroll
    for (int mi = 0; mi < 4; mi++) {
        int r = row0 + warp_m * 64 + mi * 16 + (lane >> 2);
#pragma unroll
        for (int ni = 0; ni < 4; ni++) {
            int c = col0 + warp_n * 32 + ni * 8 + (lane & 3) * 2;
            *(float2*)(C + (size_t)r * N + c) =
                make_float2(acc[mi][ni][0], acc[mi][ni][1]);
            *(float2*)(C + (size_t)(r + 8) * N + c) =
                make_float2(acc[mi][ni][2], acc[mi][ni][3]);
        }
    }
}

// ---------------------------------------------------------------------------
// RoPE (table-driven), in place on q and k.
// ---------------------------------------------------------------------------
__global__ __launch_bounds__(256)
void rope_kernel(float* __restrict__ q, float* __restrict__ k) {
    const size_t total = (size_t)BT * NHEAD * (HDIM / 2);
    size_t idx = (size_t)blockIdx.x * blockDim.x + threadIdx.x;
    if (idx >= total) return;

    int i  = (int)(idx & 63);
    int h  = (int)((idx >> 6) & (NHEAD - 1));
    int bt = (int)(idx >> 10);
    int t  = bt & (SEQ - 1);

    float2 cs = g_rope_tab[t * 64 + i];
    float c = cs.x, s = cs.y;

    size_t base = (size_t)bt * DMODEL + h * HDIM + i;

    float q1 = q[base], q2 = q[base + 64];
    q[base]      = q1 * c - q2 * s;
    q[base + 64] = q2 * c + q1 * s;

    float k1 = k[base], k2 = k[base + 64];
    k[base]      = k1 * c - k2 * s;
    k[base + 64] = k2 * c + k1 * s;
}

// ---------------------------------------------------------------------------
// Flash attention (causal, fp32, online softmax) — unchanged (passing, 2e-6).
// ---------------------------------------------------------------------------
#define FBM 64
#define FBN 64
#define QSTR 132
#define PSTR 68
#define FSMEM_FLOATS (3 * 64 * QSTR + 64 * PSTR)
#define FSMEM_BYTES  (FSMEM_FLOATS * 4)

__global__ __launch_bounds__(256)
void flash_attn(const float* __restrict__ q, const float* __restrict__ k,
                const float* __restrict__ v, float* __restrict__ o) {
    extern __shared__ float fs[];
    float* Qs = fs;
    float* Ks = Qs + 64 * QSTR;
    float* Vs = Ks + 64 * QSTR;
    float* Ps = Vs + 64 * QSTR;

    const int mb = blockIdx.x;
    const int bh = blockIdx.y;
    const int b  = bh / NHEAD;
    const int h  = bh % NHEAD;
    const int tid = threadIdx.x;
    const int tx = tid & 15;
    const int ty = tid >> 4;
    const float scale = 0.08838834764831845f;

    const float* qbase = q + (size_t)b * SEQ * DMODEL + h * HDIM;
    const float* kbase = k + (size_t)b * SEQ * DMODEL + h * HDIM;
    const float* vbase = v + (size_t)b * SEQ * DMODEL + h * HDIM;

    for (int l = tid; l < 64 * 32; l += 256) {
        int r  = l >> 5;
        int c4 = (l & 31) * 4;
        float4 t4 = *(const float4*)(qbase + (size_t)(mb * FBM + r) * DMODEL + c4);
        Qs[r * QSTR + c4 + 0] = t4.x;
        Qs[r * QSTR + c4 + 1] = t4.y;
        Qs[r * QSTR + c4 + 2] = t4.z;
        Qs[r * QSTR + c4 + 3] = t4.w;
    }

    float m_i[4], l_i[4], Oacc[4][8];
#pragma unroll
    for (int i = 0; i < 4; i++) {
        m_i[i] = -INFINITY;
        l_i[i] = 0.f;
#pragma unroll
        for (int jj = 0; jj < 8; jj++) Oacc[i][jj] = 0.f;
    }
    __syncthreads();

    for (int jb = 0; jb <= mb; jb++) {
        for (int l = tid; l < 64 * 32; l += 256) {
            int r  = l >> 5;
            int c4 = (l & 31) * 4;
            size_t goff = (size_t)(jb * FBN + r) * DMODEL + c4;
            float4 kt = *(const float4*)(kbase + goff);
            Ks[r * QSTR + c4 + 0] = kt.x;
            Ks[r * QSTR + c4 + 1] = kt.y;
            Ks[r * QSTR + c4 + 2] = kt.z;
            Ks[r * QSTR + c4 + 3] = kt.w;
            float4 vt = *(const float4*)(vbase + goff);
            Vs[r * QSTR + c4 + 0] = vt.x;
            Vs[r * QSTR + c4 + 1] = vt.y;
            Vs[r * QSTR + c4 + 2] = vt.z;
            Vs[r * QSTR + c4 + 3] = vt.w;
        }
        __syncthreads();

        float s[4][4];
#pragma unroll
        for (int i = 0; i < 4; i++)
#pragma unroll
            for (int j = 0; j < 4; j++) s[i][j] = 0.f;

        for (int kk = 0; kk < HDIM; kk += 4) {
            float4 a4[4], b4[4];
#pragma unroll
            for (int i = 0; i < 4; i++)
                a4[i] = *(const float4*)&Qs[(ty * 4 + i) * QSTR + kk];
#pragma unroll
            for (int j = 0; j < 4; j++)
                b4[j] = *(const float4*)&Ks[(tx * 4 + j) * QSTR + kk];
#pragma unroll
            for (int i = 0; i < 4; i++)
#pragma unroll
                for (int j = 0; j < 4; j++) {
                    s[i][j] = fmaf(a4[i].x, b4[j].x, s[i][j]);
                    s[i][j] = fmaf(a4[i].y, b4[j].y, s[i][j]);
                    s[i][j] = fmaf(a4[i].z, b4[j].z, s[i][j]);
                    s[i][j] = fmaf(a4[i].w, b4[j].w, s[i][j]);
                }
        }

#pragma unroll
        for (int i = 0; i < 4; i++)
#pragma unroll
            for (int j = 0; j < 4; j++) {
                s[i][j] *= scale;
                if (jb == mb && (tx * 4 + j) > (ty * 4 + i)) s[i][j] = -INFINITY;
            }

#pragma unroll
        for (int i = 0; i < 4; i++) {
            float mn = fmaxf(fmaxf(s[i][0], s[i][1]), fmaxf(s[i][2], s[i][3]));
#pragma unroll
            for (int off = 1; off < 16; off <<= 1)
                mn = fmaxf(mn, __shfl_xor_sync(0xffffffffu, mn, off));
            mn = fmaxf(mn, m_i[i]);

            float alpha = __expf(m_i[i] - mn);
            m_i[i] = mn;
            l_i[i] *= alpha;
#pragma unroll
            for (int jj = 0; jj < 8; jj++) Oacc[i][jj] *= alpha;

            float rs = 0.f;
#pragma unroll
            for (int j = 0; j < 4; j++) {
                float p = __expf(s[i][j] - mn);
                s[i][j] = p;
                rs += p;
            }
#pragma unroll
            for (int off = 1; off < 16; off <<= 1)
                rs += __shfl_xor_sync(0xffffffffu, rs, off);
            l_i[i] += rs;
        }

#pragma unroll
        for (int i = 0; i < 4; i++) {
            float4 p4 = make_float4(s[i][0], s[i][1], s[i][2], s[i][3]);
            *(float4*)&Ps[(ty * 4 + i) * PSTR + tx * 4] = p4;
        }
        __syncthreads();

        for (int kk = 0; kk < FBN; kk++) {
            float a[4];
#pragma unroll
            for (int i = 0; i < 4; i++) a[i] = Ps[(ty * 4 + i) * PSTR + kk];
            float4 vb0 = *(const float4*)&Vs[kk * QSTR + tx * 8];
            float4 vb1 = *(const float4*)&Vs[kk * QSTR + tx * 8 + 4];
            float bb[8] = {vb0.x, vb0.y, vb0.z, vb0.w, vb1.x, vb1.y, vb1.z, vb1.w};
#pragma unroll
            for (int i = 0; i < 4; i++)
#pragma unroll
                for (int jj = 0; jj < 8; jj++)
                    Oacc[i][jj] = fmaf(a[i], bb[jj], Oacc[i][jj]);
        }
        __syncthreads();
    }

    float* obase = o + (size_t)b * SEQ * DMODEL + h * HDIM;
#pragma unroll
    for (int i = 0; i < 4; i++) {
        float inv_l = 1.0f / l_i[i];
        float* orow = obase + (size_t)(mb * FBM + ty * 4 + i) * DMODEL + tx * 8;
        float4 o0 = make_float4(Oacc[i][0] * inv_l, Oacc[i][1] * inv_l,
                                Oacc[i][2] * inv_l, Oacc[i][3] * inv_l);
        float4 o1 = make_float4(Oacc[i][4] * inv_l, Oacc[i][5] * inv_l,
                                Oacc[i][6] * inv_l, Oacc[i][7] * inv_l);
        *(float4*)(orow)     = o0;
        *(float4*)(orow + 4) = o1;
    }
}

// ---------------------------------------------------------------------------
// Launch
// ---------------------------------------------------------------------------
extern "C" void kernel_launch(void* const* d_in, const int* in_sizes, int n_in,
                              void* d_out, int out_size) {
    const float* x  = (const float*)d_in[0];
    const float* wq = (const float*)d_in[1];
    const float* wk = (const float*)d_in[2];
    const float* wv = (const float*)d_in[3];
    const float* wo = (const float*)d_in[4];
    float* out = (float*)d_out;

    float *qp, *kp, *vp, *op;
    cudaGetSymbolAddress((void**)&qp, g_q);
    cudaGetSymbolAddress((void**)&kp, g_k);
    cudaGetSymbolAddress((void**)&vp, g_v);
    cudaGetSymbolAddress((void**)&op, g_o);

    __nv_bfloat16 *xhi, *xlo, *ohi, *olo;
    __nv_bfloat16 *wqhi, *wqlo, *wkhi, *wklo, *wvhi, *wvlo, *wohi, *wolo;
    cudaGetSymbolAddress((void**)&xhi, g_xhi);
    cudaGetSymbolAddress((void**)&xlo, g_xlo);
    cudaGetSymbolAddress((void**)&ohi, g_ohi);
    cudaGetSymbolAddress((void**)&olo, g_olo);
    cudaGetSymbolAddress((void**)&wqhi, g_wqhi);
    cudaGetSymbolAddress((void**)&wqlo, g_wqlo);
    cudaGetSymbolAddress((void**)&wkhi, g_wkhi);
    cudaGetSymbolAddress((void**)&wklo, g_wklo);
    cudaGetSymbolAddress((void**)&wvhi, g_wvhi);
    cudaGetSymbolAddress((void**)&wvlo, g_wvlo);
    cudaGetSymbolAddress((void**)&wohi, g_wohi);
    cudaGetSymbolAddress((void**)&wolo, g_wolo);

    // RoPE table
    rope_table_kernel<<<(SEQ * 64 + 255) / 256, 256>>>();

    // Splits
    const size_t nx = (size_t)BT * DMODEL;
    const size_t nw = (size_t)DMODEL * DMODEL;
    split_bf16<<<(int)((nx + 255) / 256), 256>>>(x,  xhi,  xlo,  nx);
    split_bf16<<<(int)((nw + 255) / 256), 256>>>(wq, wqhi, wqlo, nw);
    split_bf16<<<(int)((nw + 255) / 256), 256>>>(wk, wkhi, wklo, nw);
    split_bf16<<<(int)((nw + 255) / 256), 256>>>(wv, wvhi, wvlo, nw);
    split_bf16<<<(int)((nw + 255) / 256), 256>>>(wo, wohi, wolo, nw);

    // QKV projections (tensor cores via mma.sync)
    cudaFuncSetAttribute(gemm_bf16split,
                         cudaFuncAttributeMaxDynamicSharedMemorySize, GEMM_SMEM);
    dim3 ggrid(DMODEL / BN, BT / BM);   // (16, 64)
    gemm_bf16split<<<ggrid, 256, GEMM_SMEM>>>(xhi, xlo, wqhi, wqlo, qp, BT, DMODEL, DMODEL);
    gemm_bf16split<<<ggrid, 256, GEMM_SMEM>>>(xhi, xlo, wkhi, wklo, kp, BT, DMODEL, DMODEL);
    gemm_bf16split<<<ggrid, 256, GEMM_SMEM>>>(xhi, xlo, wvhi, wvlo, vp, BT, DMODEL, DMODEL);

    // RoPE
    {
        size_t total = (size_t)BT * NHEAD * (HDIM / 2);
        rope_kernel<<<(int)((total + 255) / 256), 256>>>(qp, kp);
    }

    // Flash attention (fp32)
    cudaFuncSetAttribute(flash_attn, cudaFuncAttributeMaxDynamicSharedMemorySize,
                         FSMEM_BYTES);
    flash_attn<<<dim3(SEQ / FBM, BATCH * NHEAD), 256, FSMEM_BYTES>>>(qp, kp, vp, op);

    // Output projection
    split_bf16<<<(int)((nx + 255) / 256), 256>>>(op, ohi, olo, nx);
    gemm_bf16split<<<ggrid, 256, GEMM_SMEM>>>(ohi, olo, wohi, wolo, out, BT, DMODEL, DMODEL);
}

// round 8
// speedup vs baseline: 2.9507x; 1.9765x over previous
#include <cuda_runtime.h>
#include <cuda_bf16.h>
#include <math.h>
#include <stdint.h>

// ---------------------------------------------------------------------------
// Problem constants
// ---------------------------------------------------------------------------
#define BATCH   4
#define SEQ     2048
#define DMODEL  2048
#define NHEAD   16
#define HDIM    128
#define BT      (BATCH * SEQ)   // 8192

__device__ __forceinline__ uint32_t smem_to_u32(const void* smem_ptr) {
    uint32_t addr;
    asm("{ .reg .u64 tmp; cvta.to.shared.u64 tmp, %1; cvt.u32.u64 %0, tmp; }"
        : "=r"(addr) : "l"(smem_ptr));
    return addr;
}

#define CP_ASYNC_16(dst_u32, src_ptr) \
    asm volatile("cp.async.cg.shared.global [%0], [%1], 16;" \
        :: "r"(dst_u32), "l"(src_ptr) : "memory")
#define CP_ASYNC_COMMIT() asm volatile("cp.async.commit_group;" ::: "memory")
#define CP_ASYNC_WAIT_1() asm volatile("cp.async.wait_group 1;" ::: "memory")
#define CP_ASYNC_WAIT_0() asm volatile("cp.async.wait_group 0;" ::: "memory")

#define LDMATRIX_X4(r0, r1, r2, r3, addr) \
    asm volatile("ldmatrix.sync.aligned.m8n8.x4.shared.b16 {%0,%1,%2,%3}, [%4];" \
        : "=r"(r0), "=r"(r1), "=r"(r2), "=r"(r3) : "r"(addr))

#define LDMATRIX_X4_TRANS(r0, r1, r2, r3, addr) \
    asm volatile("ldmatrix.sync.aligned.m8n8.x4.trans.shared.b16 {%0,%1,%2,%3}, [%4];" \
        : "=r"(r0), "=r"(r1), "=r"(r2), "=r"(r3) : "r"(addr))

#define MMA_BF16(c, a, b) \
    asm volatile( \
        "mma.sync.aligned.m16n8k16.row.col.f32.bf16.bf16.f32 " \
        "{%0,%1,%2,%3}, {%4,%5,%6,%7}, {%8,%9}, {%0,%1,%2,%3};" \
        : "+f"((c)[0]), "+f"((c)[1]), "+f"((c)[2]), "+f"((c)[3]) \
        : "r"((a)[0]), "r"((a)[1]), "r"((a)[2]), "r"((a)[3]), \
          "r"((b)[0]), "r"((b)[1]))

// pack two f32 into bf16x2: low half = lo, high half = hi
#define PACK_BF16X2(d, hi_f, lo_f) \
    asm("cvt.rn.bf16x2.f32 %0, %1, %2;" : "=r"(d) : "f"(hi_f), "f"(lo_f))

// ---------------------------------------------------------------------------
// Scratch (allocation-free rule: __device__ globals)
// ---------------------------------------------------------------------------
__device__ float g_q[(size_t)BT * DMODEL];
__device__ float g_k[(size_t)BT * DMODEL];
__device__ float g_v[(size_t)BT * DMODEL];
__device__ float g_o[(size_t)BT * DMODEL];
__device__ float2 g_rope_tab[SEQ * 64];

__device__ __nv_bfloat16 g_xhi[(size_t)BT * DMODEL];
__device__ __nv_bfloat16 g_xlo[(size_t)BT * DMODEL];
__device__ __nv_bfloat16 g_ohi[(size_t)BT * DMODEL];
__device__ __nv_bfloat16 g_olo[(size_t)BT * DMODEL];
__device__ __nv_bfloat16 g_wqhi[(size_t)DMODEL * DMODEL];
__device__ __nv_bfloat16 g_wqlo[(size_t)DMODEL * DMODEL];
__device__ __nv_bfloat16 g_wkhi[(size_t)DMODEL * DMODEL];
__device__ __nv_bfloat16 g_wklo[(size_t)DMODEL * DMODEL];
__device__ __nv_bfloat16 g_wvhi[(size_t)DMODEL * DMODEL];
__device__ __nv_bfloat16 g_wvlo[(size_t)DMODEL * DMODEL];
__device__ __nv_bfloat16 g_wohi[(size_t)DMODEL * DMODEL];
__device__ __nv_bfloat16 g_wolo[(size_t)DMODEL * DMODEL];

// bf16 hi/lo q,k,v for tensor-core flash
__device__ __nv_bfloat16 g_qhi[(size_t)BT * DMODEL];
__device__ __nv_bfloat16 g_qlo[(size_t)BT * DMODEL];
__device__ __nv_bfloat16 g_khi[(size_t)BT * DMODEL];
__device__ __nv_bfloat16 g_klo[(size_t)BT * DMODEL];
__device__ __nv_bfloat16 g_vhi[(size_t)BT * DMODEL];
__device__ __nv_bfloat16 g_vlo[(size_t)BT * DMODEL];

// ---------------------------------------------------------------------------
// fp32 -> (bf16 hi, bf16 lo) split
// ---------------------------------------------------------------------------
__global__ __launch_bounds__(256)
void split_bf16(const float* __restrict__ src,
                __nv_bfloat16* __restrict__ hi, __nv_bfloat16* __restrict__ lo,
                size_t n) {
    size_t i = (size_t)blockIdx.x * blockDim.x + threadIdx.x;
    if (i >= n) return;
    float x = src[i];
    __nv_bfloat16 h = __float2bfloat16(x);
    float r = x - __bfloat162float(h);
    hi[i] = h;
    lo[i] = __float2bfloat16(r);
}

// ---------------------------------------------------------------------------
// RoPE table in double precision (immune to --use_fast_math)
// ---------------------------------------------------------------------------
__global__ __launch_bounds__(256)
void rope_table_kernel() {
    int idx = blockIdx.x * blockDim.x + threadIdx.x;
    if (idx >= SEQ * 64) return;
    int i = idx & 63;
    int t = idx >> 6;
    float inv_freq = (float)exp(-log(10000.0) * ((double)i / 64.0));
    float ang_f = (float)t * inv_freq;
    double ang = (double)ang_f;
    g_rope_tab[idx] = make_float2((float)cos(ang), (float)sin(ang));
}

// ---------------------------------------------------------------------------
// RoPE + bf16 hi/lo split for q and k (fused)
// ---------------------------------------------------------------------------
__global__ __launch_bounds__(256)
void rope_split_kernel(const float* __restrict__ q, const float* __restrict__ k,
                       __nv_bfloat16* __restrict__ qhi, __nv_bfloat16* __restrict__ qlo,
                       __nv_bfloat16* __restrict__ khi, __nv_bfloat16* __restrict__ klo) {
    const size_t total = (size_t)BT * NHEAD * (HDIM / 2);
    size_t idx = (size_t)blockIdx.x * blockDim.x + threadIdx.x;
    if (idx >= total) return;

    int i  = (int)(idx & 63);
    int h  = (int)((idx >> 6) & (NHEAD - 1));
    int bt = (int)(idx >> 10);
    int t  = bt & (SEQ - 1);

    float2 cs = g_rope_tab[t * 64 + i];
    float c = cs.x, s = cs.y;

    size_t base = (size_t)bt * DMODEL + h * HDIM + i;

    float q1 = q[base], q2 = q[base + 64];
    float qa = q1 * c - q2 * s;
    float qb = q2 * c + q1 * s;
    __nv_bfloat16 qah = __float2bfloat16(qa);
    __nv_bfloat16 qbh = __float2bfloat16(qb);
    qhi[base]      = qah; qlo[base]      = __float2bfloat16(qa - __bfloat162float(qah));
    qhi[base + 64] = qbh; qlo[base + 64] = __float2bfloat16(qb - __bfloat162float(qbh));

    float k1 = k[base], k2 = k[base + 64];
    float ka = k1 * c - k2 * s;
    float kb = k2 * c + k1 * s;
    __nv_bfloat16 kah = __float2bfloat16(ka);
    __nv_bfloat16 kbh = __float2bfloat16(kb);
    khi[base]      = kah; klo[base]      = __float2bfloat16(ka - __bfloat162float(kah));
    khi[base + 64] = kbh; klo[base + 64] = __float2bfloat16(kb - __bfloat162float(kbh));
}

// ---------------------------------------------------------------------------
// bf16-split GEMM on mma.sync (validated R6) — unchanged.
// ---------------------------------------------------------------------------
#define BM 128
#define BN 128
#define BK 32
#define ROWB 80
#define TILE_B (128 * ROWB)
#define STAGE_B (4 * TILE_B)
#define GEMM_SMEM (2 * STAGE_B)

__global__ __launch_bounds__(256, 1)
void gemm_bf16split(const __nv_bfloat16* __restrict__ Ahi,
                    const __nv_bfloat16* __restrict__ Alo,
                    const __nv_bfloat16* __restrict__ Bhi,
                    const __nv_bfloat16* __restrict__ Blo,
                    float* __restrict__ C, int M, int N, int K) {
    extern __shared__ char smem[];
    const uint32_t sb = smem_to_u32(smem);
    const int tid  = threadIdx.x;
    const int lane = tid & 31;
    const int wid  = tid >> 5;
    const int warp_m = wid & 1;
    const int warp_n = wid >> 1;

    const int row0 = blockIdx.y * BM;
    const int col0 = blockIdx.x * BN;

    float acc[4][4][4];
#pragma unroll
    for (int mi = 0; mi < 4; mi++)
#pragma unroll
        for (int ni = 0; ni < 4; ni++)
#pragma unroll
            for (int e = 0; e < 4; e++) acc[mi][ni][e] = 0.f;

    const int r_ld  = tid >> 2;
    const int c_ld  = (tid & 3) * 16;
    const int ke_ld = (tid & 3) * 8;

    {
        const int k0 = 0;
#pragma unroll
        for (int half = 0; half < 2; half++) {
            int r = r_ld + half * 64;
            uint32_t d = sb + r * ROWB + c_ld;
            size_t ga = (size_t)(row0 + r) * K + k0 + ke_ld;
            size_t gb = (size_t)(col0 + r) * K + k0 + ke_ld;
            CP_ASYNC_16(d + 0 * TILE_B, Ahi + ga);
            CP_ASYNC_16(d + 1 * TILE_B, Alo + ga);
            CP_ASYNC_16(d + 2 * TILE_B, Bhi + gb);
            CP_ASYNC_16(d + 3 * TILE_B, Blo + gb);
        }
        CP_ASYNC_COMMIT();
    }

    const int niter = K / BK;
    for (int kt = 0; kt < niter; kt++) {
        if (kt + 1 < niter) {
            const int k0 = (kt + 1) * BK;
            const uint32_t base = sb + ((kt + 1) & 1) * STAGE_B;
#pragma unroll
            for (int half = 0; half < 2; half++) {
                int r = r_ld + half * 64;
                uint32_t d = base + r * ROWB + c_ld;
                size_t ga = (size_t)(row0 + r) * K + k0 + ke_ld;
                size_t gb = (size_t)(col0 + r) * K + k0 + ke_ld;
                CP_ASYNC_16(d + 0 * TILE_B, Ahi + ga);
                CP_ASYNC_16(d + 1 * TILE_B, Alo + ga);
                CP_ASYNC_16(d + 2 * TILE_B, Bhi + gb);
                CP_ASYNC_16(d + 3 * TILE_B, Blo + gb);
            }
        }
        CP_ASYNC_COMMIT();
        CP_ASYNC_WAIT_1();
        __syncthreads();

        const uint32_t base  = sb + (kt & 1) * STAGE_B;
        const uint32_t a_hiB = base + 0 * TILE_B;
        const uint32_t a_loB = base + 1 * TILE_B;
        const uint32_t b_hiB = base + 2 * TILE_B;
        const uint32_t b_loB = base + 3 * TILE_B;

#pragma unroll
        for (int ks = 0; ks < 2; ks++) {
            const int kb = ks * 32;

            uint32_t ah[4][4], al[4][4], bh[4][2], bl[4][2];
            const int ar = warp_m * 64 + (lane & 15);
            const uint32_t acol = kb + ((lane >> 4) << 4);
#pragma unroll
            for (int mi = 0; mi < 4; mi++) {
                uint32_t off = (uint32_t)(ar + mi * 16) * ROWB + acol;
                LDMATRIX_X4(ah[mi][0], ah[mi][1], ah[mi][2], ah[mi][3], a_hiB + off);
                LDMATRIX_X4(al[mi][0], al[mi][1], al[mi][2], al[mi][3], a_loB + off);
            }
            const int brr = warp_n * 32 + ((lane >> 4) & 1) * 8 + (lane & 7);
            const uint32_t bcol = kb + ((lane >> 3) & 1) * 16;
#pragma unroll
            for (int nb = 0; nb < 2; nb++) {
                uint32_t off = (uint32_t)(brr + nb * 16) * ROWB + bcol;
                LDMATRIX_X4(bh[2*nb][0], bh[2*nb][1], bh[2*nb+1][0], bh[2*nb+1][1],
                            b_hiB + off);
                LDMATRIX_X4(bl[2*nb][0], bl[2*nb][1], bl[2*nb+1][0], bl[2*nb+1][1],
                            b_loB + off);
            }
#pragma unroll
            for (int mi = 0; mi < 4; mi++)
#pragma unroll
                for (int ni = 0; ni < 4; ni++) {
                    MMA_BF16(acc[mi][ni], ah[mi], bh[ni]);
                    MMA_BF16(acc[mi][ni], ah[mi], bl[ni]);
                    MMA_BF16(acc[mi][ni], al[mi], bh[ni]);
                }
        }
        __syncthreads();
    }

#pragma unroll
    for (int mi = 0; mi < 4; mi++) {
        int r = row0 + warp_m * 64 + mi * 16 + (lane >> 2);
#pragma unroll
        for (int ni = 0; ni < 4; ni++) {
            int c = col0 + warp_n * 32 + ni * 8 + (lane & 3) * 2;
            *(float2*)(C + (size_t)r * N + c) =
                make_float2(acc[mi][ni][0], acc[mi][ni][1]);
            *(float2*)(C + (size_t)(r + 8) * N + c) =
                make_float2(acc[mi][ni][2], acc[mi][ni][3]);
        }
    }
}

// ---------------------------------------------------------------------------
// Tensor-core flash attention (causal, bf16 hi/lo split, fp32 accum).
// CTA: 128 threads (4 warps, each owns 16 query rows). BM=BN=64, hd=128.
// smem tiles: Qhi,Qlo,Khi,Klo,Vhi,Vlo — 64 rows x 272B (256B data + 16B pad).
// ---------------------------------------------------------------------------
#define FROWB 272
#define FTILE (64 * FROWB)       // 17408 B
#define SQH 0
#define SQL (1 * FTILE)
#define SKH (2 * FTILE)
#define SKL (3 * FTILE)
#define SVH (4 * FTILE)
#define SVL (5 * FTILE)
#define FA_SMEM (6 * FTILE)      // 104448 B

__global__ __launch_bounds__(128)
void flash_attn_tc(const __nv_bfloat16* __restrict__ qhi, const __nv_bfloat16* __restrict__ qlo,
                   const __nv_bfloat16* __restrict__ khi, const __nv_bfloat16* __restrict__ klo,
                   const __nv_bfloat16* __restrict__ vhi, const __nv_bfloat16* __restrict__ vlo,
                   float* __restrict__ o) {
    extern __shared__ char sm[];
    const uint32_t sb = smem_to_u32(sm);
    const int tid  = threadIdx.x;
    const int lane = tid & 31;
    const int warp = tid >> 5;

    const int mb = blockIdx.x;          // query tile (64 rows)
    const int bh = blockIdx.y;
    const int b  = bh >> 4;
    const int h  = bh & 15;
    const float scale = 0.08838834764831845f;   // 1/sqrt(128)

    const size_t hbase = (size_t)b * SEQ * DMODEL + (size_t)h * HDIM;

    // ---- load Q tile (hi+lo): 64 rows x 256B = 1024 x 16B chunks ----
    {
        const size_t q0 = hbase + (size_t)mb * 64 * DMODEL;
        for (int i = tid; i < 1024; i += 128) {
            int r = i >> 4, c = i & 15;
            uint32_t d = sb + r * FROWB + c * 16;
            size_t g = q0 + (size_t)r * DMODEL + c * 8;
            CP_ASYNC_16(d + SQH, qhi + g);
            CP_ASYNC_16(d + SQL, qlo + g);
        }
        CP_ASYNC_COMMIT();
    }

    const int r0 = lane >> 2;           // row within warp's 16 (c0,c1)
    float m0 = -INFINITY, m1 = -INFINITY, l0 = 0.f, l1 = 0.f;
    float oacc[16][4];
#pragma unroll
    for (int nb = 0; nb < 16; nb++)
#pragma unroll
        for (int e = 0; e < 4; e++) oacc[nb][e] = 0.f;

    for (int jb = 0; jb <= mb; jb++) {
        // ---- load K,V tiles (hi+lo): 1024 x 16B chunks each pair ----
        {
            const size_t kv0 = hbase + (size_t)jb * 64 * DMODEL;
            for (int i = tid; i < 1024; i += 128) {
                int r = i >> 4, c = i & 15;
                uint32_t d = sb + r * FROWB + c * 16;
                size_t g = kv0 + (size_t)r * DMODEL + c * 8;
                CP_ASYNC_16(d + SKH, khi + g);
                CP_ASYNC_16(d + SKL, klo + g);
                CP_ASYNC_16(d + SVH, vhi + g);
                CP_ASYNC_16(d + SVL, vlo + g);
            }
            CP_ASYNC_COMMIT();
            CP_ASYNC_WAIT_0();
            __syncthreads();
        }

        // ---- S = Q*K^T (hi/lo split, 3 passes), fp32 accum ----
        float sacc[8][4];
#pragma unroll
        for (int j = 0; j < 8; j++)
#pragma unroll
            for (int e = 0; e < 4; e++) sacc[j][e] = 0.f;

#pragma unroll
        for (int ks = 0; ks < 8; ks++) {
            const int kb = ks * 32;     // byte offset of k16 step
            uint32_t aqh[4], aql[4];
            uint32_t aaddr = sb + (uint32_t)(warp * 16 + (lane & 15)) * FROWB
                           + kb + ((lane >> 4) << 4);
            LDMATRIX_X4(aqh[0], aqh[1], aqh[2], aqh[3], aaddr + SQH);
            LDMATRIX_X4(aql[0], aql[1], aql[2], aql[3], aaddr + SQL);
#pragma unroll
            for (int nsl = 0; nsl < 4; nsl++) {
                uint32_t bkh[2][2], bkl[2][2];
                uint32_t baddr = sb
                    + (uint32_t)(nsl * 16 + ((lane >> 4) & 1) * 8 + (lane & 7)) * FROWB
                    + kb + ((lane >> 3) & 1) * 16;
                LDMATRIX_X4(bkh[0][0], bkh[0][1], bkh[1][0], bkh[1][1], baddr + SKH);
                LDMATRIX_X4(bkl[0][0], bkl[0][1], bkl[1][0], bkl[1][1], baddr + SKL);
#pragma unroll
                for (int t = 0; t < 2; t++) {
                    int j = nsl * 2 + t;
                    MMA_BF16(sacc[j], aqh, bkh[t]);
                    MMA_BF16(sacc[j], aqh, bkl[t]);
                    MMA_BF16(sacc[j], aql, bkh[t]);
                }
            }
        }

        // ---- scale + causal mask (diagonal tile only) ----
#pragma unroll
        for (int j = 0; j < 8; j++)
#pragma unroll
            for (int e = 0; e < 4; e++) sacc[j][e] *= scale;

        if (jb == mb) {
            const int row0 = warp * 16 + r0;
            const int row1 = row0 + 8;
#pragma unroll
            for (int j = 0; j < 8; j++) {
                int c0 = j * 8 + (lane & 3) * 2;
                if (c0     > row0) sacc[j][0] = -INFINITY;
                if (c0 + 1 > row0) sacc[j][1] = -INFINITY;
                if (c0     > row1) sacc[j][2] = -INFINITY;
                if (c0 + 1 > row1) sacc[j][3] = -INFINITY;
            }
        }

        // ---- online softmax (rows r0, r0+8; quad-lane reductions) ----
        float mn0 = -INFINITY, mn1 = -INFINITY;
#pragma unroll
        for (int j = 0; j < 8; j++) {
            mn0 = fmaxf(mn0, fmaxf(sacc[j][0], sacc[j][1]));
            mn1 = fmaxf(mn1, fmaxf(sacc[j][2], sacc[j][3]));
        }
        mn0 = fmaxf(mn0, __shfl_xor_sync(0xffffffffu, mn0, 1));
        mn0 = fmaxf(mn0, __shfl_xor_sync(0xffffffffu, mn0, 2));
        mn1 = fmaxf(mn1, __shfl_xor_sync(0xffffffffu, mn1, 1));
        mn1 = fmaxf(mn1, __shfl_xor_sync(0xffffffffu, mn1, 2));
        mn0 = fmaxf(mn0, m0);
        mn1 = fmaxf(mn1, m1);

        float alpha0 = __expf(m0 - mn0);
        float alpha1 = __expf(m1 - mn1);
        m0 = mn0; m1 = mn1;
        l0 *= alpha0; l1 *= alpha1;
#pragma unroll
        for (int nb = 0; nb < 16; nb++) {
            oacc[nb][0] *= alpha0; oacc[nb][1] *= alpha0;
            oacc[nb][2] *= alpha1; oacc[nb][3] *= alpha1;
        }

        float rs0 = 0.f, rs1 = 0.f;
#pragma unroll
        for (int j = 0; j < 8; j++) {
            float p0 = __expf(sacc[j][0] - mn0);
            float p1 = __expf(sacc[j][1] - mn0);
            float p2 = __expf(sacc[j][2] - mn1);
            float p3 = __expf(sacc[j][3] - mn1);
            sacc[j][0] = p0; sacc[j][1] = p1; sacc[j][2] = p2; sacc[j][3] = p3;
            rs0 += p0 + p1; rs1 += p2 + p3;
        }
        rs0 += __shfl_xor_sync(0xffffffffu, rs0, 1);
        rs0 += __shfl_xor_sync(0xffffffffu, rs0, 2);
        rs1 += __shfl_xor_sync(0xffffffffu, rs1, 1);
        rs1 += __shfl_xor_sync(0xffffffffu, rs1, 2);
        l0 += rs0; l1 += rs1;

        // ---- P fragments (hi/lo) directly from S accumulators ----
        uint32_t aph[4][4], apl[4][4];
#pragma unroll
        for (int kb2 = 0; kb2 < 4; kb2++) {
            int j = kb2 * 2;
#pragma unroll
            for (int q = 0; q < 4; q++) {
                int jj = j + (q >> 1);
                int e0 = (q & 1) * 2;
                float p0 = sacc[jj][e0], p1 = sacc[jj][e0 + 1];
                float h0 = __bfloat162float(__float2bfloat16(p0));
                float h1 = __bfloat162float(__float2bfloat16(p1));
                PACK_BF16X2(aph[kb2][q], h1, h0);
                PACK_BF16X2(apl[kb2][q], p1 - h1, p0 - h0);
            }
        }

        // ---- O += P*V (hi/lo split, 3 passes), V via ldmatrix.trans ----
#pragma unroll
        for (int kb2 = 0; kb2 < 4; kb2++) {
#pragma unroll
            for (int ns2 = 0; ns2 < 8; ns2++) {
                uint32_t bvh[2][2], bvl[2][2];
                uint32_t vaddr = sb
                    + (uint32_t)(kb2 * 16 + (lane & 7) + ((lane >> 3) & 1) * 8) * FROWB
                    + ns2 * 32 + ((lane >> 4) & 1) * 16;
                LDMATRIX_X4_TRANS(bvh[0][0], bvh[0][1], bvh[1][0], bvh[1][1], vaddr + SVH);
                LDMATRIX_X4_TRANS(bvl[0][0], bvl[0][1], bvl[1][0], bvl[1][1], vaddr + SVL);
#pragma unroll
                for (int t = 0; t < 2; t++) {
                    int nb = ns2 * 2 + t;
                    MMA_BF16(oacc[nb], aph[kb2], bvh[t]);
                    MMA_BF16(oacc[nb], apl[kb2], bvh[t]);
                    MMA_BF16(oacc[nb], aph[kb2], bvl[t]);
                }
            }
        }
        __syncthreads();   // smem K/V reused next iteration
    }

    // ---- normalize + write ----
    const float inv0 = 1.0f / l0;
    const float inv1 = 1.0f / l1;
    float* ob = o + hbase + (size_t)(mb * 64 + warp * 16) * DMODEL;
#pragma unroll
    for (int nb = 0; nb < 16; nb++) {
        int c = nb * 8 + (lane & 3) * 2;
        *(float2*)(ob + (size_t)r0 * DMODEL + c) =
            make_float2(oacc[nb][0] * inv0, oacc[nb][1] * inv0);
        *(float2*)(ob + (size_t)(r0 + 8) * DMODEL + c) =
            make_float2(oacc[nb][2] * inv1, oacc[nb][3] * inv1);
    }
}

// ---------------------------------------------------------------------------
// Launch
// ---------------------------------------------------------------------------
extern "C" void kernel_launch(void* const* d_in, const int* in_sizes, int n_in,
                              void* d_out, int out_size) {
    const float* x  = (const float*)d_in[0];
    const float* wq = (const float*)d_in[1];
    const float* wk = (const float*)d_in[2];
    const float* wv = (const float*)d_in[3];
    const float* wo = (const float*)d_in[4];
    float* out = (float*)d_out;

    float *qp, *kp, *vp, *op;
    cudaGetSymbolAddress((void**)&qp, g_q);
    cudaGetSymbolAddress((void**)&kp, g_k);
    cudaGetSymbolAddress((void**)&vp, g_v);
    cudaGetSymbolAddress((void**)&op, g_o);

    __nv_bfloat16 *xhi, *xlo, *ohi, *olo;
    __nv_bfloat16 *wqhi, *wqlo, *wkhi, *wklo, *wvhi, *wvlo, *wohi, *wolo;
    __nv_bfloat16 *qhi, *qlo, *khi, *klo, *vhi, *vlo;
    cudaGetSymbolAddress((void**)&xhi, g_xhi);
    cudaGetSymbolAddress((void**)&xlo, g_xlo);
    cudaGetSymbolAddress((void**)&ohi, g_ohi);
    cudaGetSymbolAddress((void**)&olo, g_olo);
    cudaGetSymbolAddress((void**)&wqhi, g_wqhi);
    cudaGetSymbolAddress((void**)&wqlo, g_wqlo);
    cudaGetSymbolAddress((void**)&wkhi, g_wkhi);
    cudaGetSymbolAddress((void**)&wklo, g_wklo);
    cudaGetSymbolAddress((void**)&wvhi, g_wvhi);
    cudaGetSymbolAddress((void**)&wvlo, g_wvlo);
    cudaGetSymbolAddress((void**)&wohi, g_wohi);
    cudaGetSymbolAddress((void**)&wolo, g_wolo);
    cudaGetSymbolAddress((void**)&qhi, g_qhi);
    cudaGetSymbolAddress((void**)&qlo, g_qlo);
    cudaGetSymbolAddress((void**)&khi, g_khi);
    cudaGetSymbolAddress((void**)&klo, g_klo);
    cudaGetSymbolAddress((void**)&vhi, g_vhi);
    cudaGetSymbolAddress((void**)&vlo, g_vlo);

    // RoPE table
    rope_table_kernel<<<(SEQ * 64 + 255) / 256, 256>>>();

    // Splits of inputs/weights
    const size_t nx = (size_t)BT * DMODEL;
    const size_t nw = (size_t)DMODEL * DMODEL;
    split_bf16<<<(int)((nx + 255) / 256), 256>>>(x,  xhi,  xlo,  nx);
    split_bf16<<<(int)((nw + 255) / 256), 256>>>(wq, wqhi, wqlo, nw);
    split_bf16<<<(int)((nw + 255) / 256), 256>>>(wk, wkhi, wklo, nw);
    split_bf16<<<(int)((nw + 255) / 256), 256>>>(wv, wvhi, wvlo, nw);
    split_bf16<<<(int)((nw + 255) / 256), 256>>>(wo, wohi, wolo, nw);

    // QKV projections (tensor cores)
    cudaFuncSetAttribute(gemm_bf16split,
                         cudaFuncAttributeMaxDynamicSharedMemorySize, GEMM_SMEM);
    dim3 ggrid(DMODEL / BN, BT / BM);   // (16, 64)
    gemm_bf16split<<<ggrid, 256, GEMM_SMEM>>>(xhi, xlo, wqhi, wqlo, qp, BT, DMODEL, DMODEL);
    gemm_bf16split<<<ggrid, 256, GEMM_SMEM>>>(xhi, xlo, wkhi, wklo, kp, BT, DMODEL, DMODEL);
    gemm_bf16split<<<ggrid, 256, GEMM_SMEM>>>(xhi, xlo, wvhi, wvlo, vp, BT, DMODEL, DMODEL);

    // RoPE fused with q/k bf16 split; v split separately
    {
        size_t total = (size_t)BT * NHEAD * (HDIM / 2);
        rope_split_kernel<<<(int)((total + 255) / 256), 256>>>(qp, kp, qhi, qlo, khi, klo);
    }
    split_bf16<<<(int)((nx + 255) / 256), 256>>>(vp, vhi, vlo, nx);

    // Tensor-core flash attention
    cudaFuncSetAttribute(flash_attn_tc,
                         cudaFuncAttributeMaxDynamicSharedMemorySize, FA_SMEM);
    flash_attn_tc<<<dim3(SEQ / 64, BATCH * NHEAD), 128, FA_SMEM>>>(
        qhi, qlo, khi, klo, vhi, vlo, op);

    // Output projection
    split_bf16<<<(int)((nx + 255) / 256), 256>>>(op, ohi, olo, nx);
    gemm_bf16split<<<ggrid, 256, GEMM_SMEM>>>(ohi, olo, wohi, wolo, out, BT, DMODEL, DMODEL);
}

// round 10
// speedup vs baseline: 3.0325x; 1.0277x over previous
#include <cuda_runtime.h>
#include <cuda_bf16.h>
#include <math.h>
#include <stdint.h>

// ---------------------------------------------------------------------------
// Problem constants
// ---------------------------------------------------------------------------
#define BATCH   4
#define SEQ     2048
#define DMODEL  2048
#define NHEAD   16
#define HDIM    128
#define BT      (BATCH * SEQ)   // 8192

__device__ __forceinline__ uint32_t smem_to_u32(const void* smem_ptr) {
    uint32_t addr;
    asm("{ .reg .u64 tmp; cvta.to.shared.u64 tmp, %1; cvt.u32.u64 %0, tmp; }"
        : "=r"(addr) : "l"(smem_ptr));
    return addr;
}

#define CP_ASYNC_16(dst_u32, src_ptr) \
    asm volatile("cp.async.cg.shared.global [%0], [%1], 16;" \
        :: "r"(dst_u32), "l"(src_ptr) : "memory")
#define CP_ASYNC_COMMIT() asm volatile("cp.async.commit_group;" ::: "memory")
#define CP_ASYNC_WAIT_1() asm volatile("cp.async.wait_group 1;" ::: "memory")
#define CP_ASYNC_WAIT_0() asm volatile("cp.async.wait_group 0;" ::: "memory")

#define LDMATRIX_X4(r0, r1, r2, r3, addr) \
    asm volatile("ldmatrix.sync.aligned.m8n8.x4.shared.b16 {%0,%1,%2,%3}, [%4];" \
        : "=r"(r0), "=r"(r1), "=r"(r2), "=r"(r3) : "r"(addr))

#define LDMATRIX_X4_TRANS(r0, r1, r2, r3, addr) \
    asm volatile("ldmatrix.sync.aligned.m8n8.x4.trans.shared.b16 {%0,%1,%2,%3}, [%4];" \
        : "=r"(r0), "=r"(r1), "=r"(r2), "=r"(r3) : "r"(addr))

#define MMA_BF16(c, a, b) \
    asm volatile( \
        "mma.sync.aligned.m16n8k16.row.col.f32.bf16.bf16.f32 " \
        "{%0,%1,%2,%3}, {%4,%5,%6,%7}, {%8,%9}, {%0,%1,%2,%3};" \
        : "+f"((c)[0]), "+f"((c)[1]), "+f"((c)[2]), "+f"((c)[3]) \
        : "r"((a)[0]), "r"((a)[1]), "r"((a)[2]), "r"((a)[3]), \
          "r"((b)[0]), "r"((b)[1]))

#define PACK_BF16X2(d, hi_f, lo_f) \
    asm("cvt.rn.bf16x2.f32 %0, %1, %2;" : "=r"(d) : "f"(hi_f), "f"(lo_f))

// ---------------------------------------------------------------------------
// Scratch (allocation-free rule: __device__ globals)
// ---------------------------------------------------------------------------
__device__ float g_q[(size_t)BT * DMODEL];
__device__ float g_k[(size_t)BT * DMODEL];
__device__ float2 g_rope_tab[SEQ * 64];

__device__ __nv_bfloat16 g_xhi[(size_t)BT * DMODEL];
__device__ __nv_bfloat16 g_xlo[(size_t)BT * DMODEL];
__device__ __nv_bfloat16 g_ohi[(size_t)BT * DMODEL];
__device__ __nv_bfloat16 g_olo[(size_t)BT * DMODEL];
__device__ __nv_bfloat16 g_wqhi[(size_t)DMODEL * DMODEL];
__device__ __nv_bfloat16 g_wqlo[(size_t)DMODEL * DMODEL];
__device__ __nv_bfloat16 g_wkhi[(size_t)DMODEL * DMODEL];
__device__ __nv_bfloat16 g_wklo[(size_t)DMODEL * DMODEL];
__device__ __nv_bfloat16 g_wvhi[(size_t)DMODEL * DMODEL];
__device__ __nv_bfloat16 g_wvlo[(size_t)DMODEL * DMODEL];
__device__ __nv_bfloat16 g_wohi[(size_t)DMODEL * DMODEL];
__device__ __nv_bfloat16 g_wolo[(size_t)DMODEL * DMODEL];

__device__ __nv_bfloat16 g_qhi[(size_t)BT * DMODEL];
__device__ __nv_bfloat16 g_qlo[(size_t)BT * DMODEL];
__device__ __nv_bfloat16 g_khi[(size_t)BT * DMODEL];
__device__ __nv_bfloat16 g_klo[(size_t)BT * DMODEL];
__device__ __nv_bfloat16 g_vhi[(size_t)BT * DMODEL];
__device__ __nv_bfloat16 g_vlo[(size_t)BT * DMODEL];

// ---------------------------------------------------------------------------
// Vectorized fp32 -> (bf16 hi, bf16 lo) split: 8 elems/thread
// ---------------------------------------------------------------------------
__global__ __launch_bounds__(256)
void split_bf16_v8(const float* __restrict__ src,
                   __nv_bfloat16* __restrict__ hi, __nv_bfloat16* __restrict__ lo,
                   size_t n) {
    size_t i8 = ((size_t)blockIdx.x * 256 + threadIdx.x) * 8;
    if (i8 >= n) return;
    float4 a = *(const float4*)(src + i8);
    float4 b = *(const float4*)(src + i8 + 4);
    float v[8] = {a.x, a.y, a.z, a.w, b.x, b.y, b.z, b.w};
    __nv_bfloat162 ph[4], pl[4];
#pragma unroll
    for (int j = 0; j < 4; j++) {
        __nv_bfloat16 h0 = __float2bfloat16(v[2*j]);
        __nv_bfloat16 h1 = __float2bfloat16(v[2*j+1]);
        ph[j].x = h0; ph[j].y = h1;
        pl[j].x = __float2bfloat16(v[2*j]   - __bfloat162float(h0));
        pl[j].y = __float2bfloat16(v[2*j+1] - __bfloat162float(h1));
    }
    *(uint4*)(hi + i8) = *(uint4*)ph;
    *(uint4*)(lo + i8) = *(uint4*)pl;
}

// ---------------------------------------------------------------------------
// RoPE table in double precision (immune to --use_fast_math)
// ---------------------------------------------------------------------------
__global__ __launch_bounds__(256)
void rope_table_kernel() {
    int idx = blockIdx.x * blockDim.x + threadIdx.x;
    if (idx >= SEQ * 64) return;
    int i = idx & 63;
    int t = idx >> 6;
    float inv_freq = (float)exp(-log(10000.0) * ((double)i / 64.0));
    float ang_f = (float)t * inv_freq;
    double ang = (double)ang_f;
    g_rope_tab[idx] = make_float2((float)cos(ang), (float)sin(ang));
}

// ---------------------------------------------------------------------------
// RoPE + bf16 hi/lo split for q and k (fused)
// ---------------------------------------------------------------------------
__global__ __launch_bounds__(256)
void rope_split_kernel() {
    const size_t total = (size_t)BT * NHEAD * (HDIM / 2);
    size_t idx = (size_t)blockIdx.x * blockDim.x + threadIdx.x;
    if (idx >= total) return;

    int i  = (int)(idx & 63);
    int h  = (int)((idx >> 6) & (NHEAD - 1));
    int bt = (int)(idx >> 10);
    int t  = bt & (SEQ - 1);

    float2 cs = g_rope_tab[t * 64 + i];
    float c = cs.x, s = cs.y;

    size_t base = (size_t)bt * DMODEL + h * HDIM + i;

    float q1 = g_q[base], q2 = g_q[base + 64];
    float qa = q1 * c - q2 * s;
    float qb = q2 * c + q1 * s;
    __nv_bfloat16 qah = __float2bfloat16(qa);
    __nv_bfloat16 qbh = __float2bfloat16(qb);
    g_qhi[base]      = qah; g_qlo[base]      = __float2bfloat16(qa - __bfloat162float(qah));
    g_qhi[base + 64] = qbh; g_qlo[base + 64] = __float2bfloat16(qb - __bfloat162float(qbh));

    float k1 = g_k[base], k2 = g_k[base + 64];
    float ka = k1 * c - k2 * s;
    float kb = k2 * c + k1 * s;
    __nv_bfloat16 kah = __float2bfloat16(ka);
    __nv_bfloat16 kbh = __float2bfloat16(kb);
    g_khi[base]      = kah; g_klo[base]      = __float2bfloat16(ka - __bfloat162float(kah));
    g_khi[base + 64] = kbh; g_klo[base + 64] = __float2bfloat16(kb - __bfloat162float(kbh));
}

// ---------------------------------------------------------------------------
// bf16-split GEMM core (validated R6/R8). Epilogue writes either fp32 C or
// bf16 hi/lo pair (for the V path, fusing the split).
// ---------------------------------------------------------------------------
#define BM 128
#define BN 128
#define BK 32
#define ROWB 80
#define TILE_B (128 * ROWB)
#define STAGE_B (4 * TILE_B)
#define GEMM_SMEM (2 * STAGE_B)

__device__ __forceinline__
void gemm_body(const __nv_bfloat16* __restrict__ Ahi,
               const __nv_bfloat16* __restrict__ Alo,
               const __nv_bfloat16* __restrict__ Bhi,
               const __nv_bfloat16* __restrict__ Blo,
               float* __restrict__ Cf,
               __nv_bfloat16* __restrict__ Chi,
               __nv_bfloat16* __restrict__ Clo,
               int N, int K, char* smem) {
    const uint32_t sb = smem_to_u32(smem);
    const int tid  = threadIdx.x;
    const int lane = tid & 31;
    const int wid  = tid >> 5;
    const int warp_m = wid & 1;
    const int warp_n = wid >> 1;

    const int row0 = blockIdx.y * BM;
    const int col0 = blockIdx.x * BN;

    float acc[4][4][4];
#pragma unroll
    for (int mi = 0; mi < 4; mi++)
#pragma unroll
        for (int ni = 0; ni < 4; ni++)
#pragma unroll
            for (int e = 0; e < 4; e++) acc[mi][ni][e] = 0.f;

    const int r_ld  = tid >> 2;
    const int c_ld  = (tid & 3) * 16;
    const int ke_ld = (tid & 3) * 8;

    {
#pragma unroll
        for (int half = 0; half < 2; half++) {
            int r = r_ld + half * 64;
            uint32_t d = sb + r * ROWB + c_ld;
            size_t ga = (size_t)(row0 + r) * K + ke_ld;
            size_t gb = (size_t)(col0 + r) * K + ke_ld;
            CP_ASYNC_16(d + 0 * TILE_B, Ahi + ga);
            CP_ASYNC_16(d + 1 * TILE_B, Alo + ga);
            CP_ASYNC_16(d + 2 * TILE_B, Bhi + gb);
            CP_ASYNC_16(d + 3 * TILE_B, Blo + gb);
        }
        CP_ASYNC_COMMIT();
    }

    const int niter = K / BK;
    for (int kt = 0; kt < niter; kt++) {
        if (kt + 1 < niter) {
            const int k0 = (kt + 1) * BK;
            const uint32_t base = sb + ((kt + 1) & 1) * STAGE_B;
#pragma unroll
            for (int half = 0; half < 2; half++) {
                int r = r_ld + half * 64;
                uint32_t d = base + r * ROWB + c_ld;
                size_t ga = (size_t)(row0 + r) * K + k0 + ke_ld;
                size_t gb = (size_t)(col0 + r) * K + k0 + ke_ld;
                CP_ASYNC_16(d + 0 * TILE_B, Ahi + ga);
                CP_ASYNC_16(d + 1 * TILE_B, Alo + ga);
                CP_ASYNC_16(d + 2 * TILE_B, Bhi + gb);
                CP_ASYNC_16(d + 3 * TILE_B, Blo + gb);
            }
        }
        CP_ASYNC_COMMIT();
        CP_ASYNC_WAIT_1();
        __syncthreads();

        const uint32_t base  = sb + (kt & 1) * STAGE_B;
        const uint32_t a_hiB = base + 0 * TILE_B;
        const uint32_t a_loB = base + 1 * TILE_B;
        const uint32_t b_hiB = base + 2 * TILE_B;
        const uint32_t b_loB = base + 3 * TILE_B;

#pragma unroll
        for (int ks = 0; ks < 2; ks++) {
            const int kb = ks * 32;

            uint32_t ah[4][4], al[4][4], bh[4][2], bl[4][2];
            const int ar = warp_m * 64 + (lane & 15);
            const uint32_t acol = kb + ((lane >> 4) << 4);
#pragma unroll
            for (int mi = 0; mi < 4; mi++) {
                uint32_t off = (uint32_t)(ar + mi * 16) * ROWB + acol;
                LDMATRIX_X4(ah[mi][0], ah[mi][1], ah[mi][2], ah[mi][3], a_hiB + off);
                LDMATRIX_X4(al[mi][0], al[mi][1], al[mi][2], al[mi][3], a_loB + off);
            }
            const int brr = warp_n * 32 + ((lane >> 4) & 1) * 8 + (lane & 7);
            const uint32_t bcol = kb + ((lane >> 3) & 1) * 16;
#pragma unroll
            for (int nb = 0; nb < 2; nb++) {
                uint32_t off = (uint32_t)(brr + nb * 16) * ROWB + bcol;
                LDMATRIX_X4(bh[2*nb][0], bh[2*nb][1], bh[2*nb+1][0], bh[2*nb+1][1],
                            b_hiB + off);
                LDMATRIX_X4(bl[2*nb][0], bl[2*nb][1], bl[2*nb+1][0], bl[2*nb+1][1],
                            b_loB + off);
            }
#pragma unroll
            for (int mi = 0; mi < 4; mi++)
#pragma unroll
                for (int ni = 0; ni < 4; ni++) {
                    MMA_BF16(acc[mi][ni], ah[mi], bh[ni]);
                    MMA_BF16(acc[mi][ni], ah[mi], bl[ni]);
                    MMA_BF16(acc[mi][ni], al[mi], bh[ni]);
                }
        }
        __syncthreads();
    }

#pragma unroll
    for (int mi = 0; mi < 4; mi++) {
        int r = row0 + warp_m * 64 + mi * 16 + (lane >> 2);
#pragma unroll
        for (int ni = 0; ni < 4; ni++) {
            int c = col0 + warp_n * 32 + ni * 8 + (lane & 3) * 2;
            if (Cf) {
                *(float2*)(Cf + (size_t)r * N + c) =
                    make_float2(acc[mi][ni][0], acc[mi][ni][1]);
                *(float2*)(Cf + (size_t)(r + 8) * N + c) =
                    make_float2(acc[mi][ni][2], acc[mi][ni][3]);
            } else {
#pragma unroll
                for (int rr = 0; rr < 2; rr++) {
                    float v0 = acc[mi][ni][rr*2], v1 = acc[mi][ni][rr*2+1];
                    __nv_bfloat162 ph, pl;
                    ph.x = __float2bfloat16(v0);
                    ph.y = __float2bfloat16(v1);
                    pl.x = __float2bfloat16(v0 - __bfloat162float(ph.x));
                    pl.y = __float2bfloat16(v1 - __bfloat162float(ph.y));
                    size_t off = (size_t)(r + rr * 8) * N + c;
                    *(__nv_bfloat162*)(Chi + off) = ph;
                    *(__nv_bfloat162*)(Clo + off) = pl;
                }
            }
        }
    }
}

// Fused QKV: z selects weight set; z=2 (V) writes bf16 hi/lo directly.
__global__ __launch_bounds__(256, 1)
void gemm_qkv() {
    extern __shared__ char smem[];
    const int z = blockIdx.z;
    if (z == 0)
        gemm_body(g_xhi, g_xlo, g_wqhi, g_wqlo, g_q, nullptr, nullptr,
                  DMODEL, DMODEL, smem);
    else if (z == 1)
        gemm_body(g_xhi, g_xlo, g_wkhi, g_wklo, g_k, nullptr, nullptr,
                  DMODEL, DMODEL, smem);
    else
        gemm_body(g_xhi, g_xlo, g_wvhi, g_wvlo, nullptr, g_vhi, g_vlo,
                  DMODEL, DMODEL, smem);
}

// Output projection: reads ohi/olo (written by flash) and wo, writes fp32 out.
__global__ __launch_bounds__(256, 1)
void gemm_out(float* __restrict__ out) {
    extern __shared__ char smem[];
    gemm_body(g_ohi, g_olo, g_wohi, g_wolo, out, nullptr, nullptr,
              DMODEL, DMODEL, smem);
}

// ---------------------------------------------------------------------------
// Tensor-core flash attention (causal, bf16 hi/lo split, fp32 accum).
// Writes O directly as bf16 hi/lo (fused split for the output projection).
// ---------------------------------------------------------------------------
#define FROWB 272
#define FTILE (64 * FROWB)
#define SQH 0
#define SQL (1 * FTILE)
#define SKH (2 * FTILE)
#define SKL (3 * FTILE)
#define SVH (4 * FTILE)
#define SVL (5 * FTILE)
#define FA_SMEM (6 * FTILE)      // 104448 B

__global__ __launch_bounds__(128)
void flash_attn_tc() {
    extern __shared__ char sm[];
    const uint32_t sb = smem_to_u32(sm);
    const int tid  = threadIdx.x;
    const int lane = tid & 31;
    const int warp = tid >> 5;

    const int mb = (int)gridDim.x - 1 - (int)blockIdx.x;  // heavy tiles first
    const int bh = blockIdx.y;
    const int b  = bh >> 4;
    const int h  = bh & 15;
    const float scale = 0.08838834764831845f;

    const size_t hbase = (size_t)b * SEQ * DMODEL + (size_t)h * HDIM;

    // ---- load Q tile (hi+lo): 64 rows x 256B = 1024 x 16B chunks ----
    {
        const size_t q0 = hbase + (size_t)mb * 64 * DMODEL;
        for (int i = tid; i < 1024; i += 128) {
            int r = i >> 4, c = i & 15;
            uint32_t d = sb + r * FROWB + c * 16;
            size_t g = q0 + (size_t)r * DMODEL + c * 8;
            CP_ASYNC_16(d + SQH, g_qhi + g);
            CP_ASYNC_16(d + SQL, g_qlo + g);
        }
        CP_ASYNC_COMMIT();
    }

    const int r0 = lane >> 2;
    float m0 = -INFINITY, m1 = -INFINITY, l0 = 0.f, l1 = 0.f;
    float oacc[16][4];
#pragma unroll
    for (int nb = 0; nb < 16; nb++)
#pragma unroll
        for (int e = 0; e < 4; e++) oacc[nb][e] = 0.f;

    for (int jb = 0; jb <= mb; jb++) {
        {
            const size_t kv0 = hbase + (size_t)jb * 64 * DMODEL;
            for (int i = tid; i < 1024; i += 128) {
                int r = i >> 4, c = i & 15;
                uint32_t d = sb + r * FROWB + c * 16;
                size_t g = kv0 + (size_t)r * DMODEL + c * 8;
                CP_ASYNC_16(d + SKH, g_khi + g);
                CP_ASYNC_16(d + SKL, g_klo + g);
                CP_ASYNC_16(d + SVH, g_vhi + g);
                CP_ASYNC_16(d + SVL, g_vlo + g);
            }
            CP_ASYNC_COMMIT();
            CP_ASYNC_WAIT_0();
            __syncthreads();
        }

        // ---- S = Q*K^T (hi/lo split, 3 passes) ----
        float sacc[8][4];
#pragma unroll
        for (int j = 0; j < 8; j++)
#pragma unroll
            for (int e = 0; e < 4; e++) sacc[j][e] = 0.f;

#pragma unroll
        for (int ks = 0; ks < 8; ks++) {
            const int kb = ks * 32;
            uint32_t aqh[4], aql[4];
            uint32_t aaddr = sb + (uint32_t)(warp * 16 + (lane & 15)) * FROWB
                           + kb + ((lane >> 4) << 4);
            LDMATRIX_X4(aqh[0], aqh[1], aqh[2], aqh[3], aaddr + SQH);
            LDMATRIX_X4(aql[0], aql[1], aql[2], aql[3], aaddr + SQL);
#pragma unroll
            for (int nsl = 0; nsl < 4; nsl++) {
                uint32_t bkh[2][2], bkl[2][2];
                uint32_t baddr = sb
                    + (uint32_t)(nsl * 16 + ((lane >> 4) & 1) * 8 + (lane & 7)) * FROWB
                    + kb + ((lane >> 3) & 1) * 16;
                LDMATRIX_X4(bkh[0][0], bkh[0][1], bkh[1][0], bkh[1][1], baddr + SKH);
                LDMATRIX_X4(bkl[0][0], bkl[0][1], bkl[1][0], bkl[1][1], baddr + SKL);
#pragma unroll
                for (int t = 0; t < 2; t++) {
                    int j = nsl * 2 + t;
                    MMA_BF16(sacc[j], aqh, bkh[t]);
                    MMA_BF16(sacc[j], aqh, bkl[t]);
                    MMA_BF16(sacc[j], aql, bkh[t]);
                }
            }
        }

#pragma unroll
        for (int j = 0; j < 8; j++)
#pragma unroll
            for (int e = 0; e < 4; e++) sacc[j][e] *= scale;

        if (jb == mb) {
            const int row0 = warp * 16 + r0;
            const int row1 = row0 + 8;
#pragma unroll
            for (int j = 0; j < 8; j++) {
                int c0 = j * 8 + (lane & 3) * 2;
                if (c0     > row0) sacc[j][0] = -INFINITY;
                if (c0 + 1 > row0) sacc[j][1] = -INFINITY;
                if (c0     > row1) sacc[j][2] = -INFINITY;
                if (c0 + 1 > row1) sacc[j][3] = -INFINITY;
            }
        }

        // ---- online softmax ----
        float mn0 = -INFINITY, mn1 = -INFINITY;
#pragma unroll
        for (int j = 0; j < 8; j++) {
            mn0 = fmaxf(mn0, fmaxf(sacc[j][0], sacc[j][1]));
            mn1 = fmaxf(mn1, fmaxf(sacc[j][2], sacc[j][3]));
        }
        mn0 = fmaxf(mn0, __shfl_xor_sync(0xffffffffu, mn0, 1));
        mn0 = fmaxf(mn0, __shfl_xor_sync(0xffffffffu, mn0, 2));
        mn1 = fmaxf(mn1, __shfl_xor_sync(0xffffffffu, mn1, 1));
        mn1 = fmaxf(mn1, __shfl_xor_sync(0xffffffffu, mn1, 2));
        mn0 = fmaxf(mn0, m0);
        mn1 = fmaxf(mn1, m1);

        float alpha0 = __expf(m0 - mn0);
        float alpha1 = __expf(m1 - mn1);
        m0 = mn0; m1 = mn1;
        l0 *= alpha0; l1 *= alpha1;
#pragma unroll
        for (int nb = 0; nb < 16; nb++) {
            oacc[nb][0] *= alpha0; oacc[nb][1] *= alpha0;
            oacc[nb][2] *= alpha1; oacc[nb][3] *= alpha1;
        }

        float rs0 = 0.f, rs1 = 0.f;
#pragma unroll
        for (int j = 0; j < 8; j++) {
            float p0 = __expf(sacc[j][0] - mn0);
            float p1 = __expf(sacc[j][1] - mn0);
            float p2 = __expf(sacc[j][2] - mn1);
            float p3 = __expf(sacc[j][3] - mn1);
            sacc[j][0] = p0; sacc[j][1] = p1; sacc[j][2] = p2; sacc[j][3] = p3;
            rs0 += p0 + p1; rs1 += p2 + p3;
        }
        rs0 += __shfl_xor_sync(0xffffffffu, rs0, 1);
        rs0 += __shfl_xor_sync(0xffffffffu, rs0, 2);
        rs1 += __shfl_xor_sync(0xffffffffu, rs1, 1);
        rs1 += __shfl_xor_sync(0xffffffffu, rs1, 2);
        l0 += rs0; l1 += rs1;

        // ---- P fragments (hi/lo) directly from S accumulators ----
        uint32_t aph[4][4], apl[4][4];
#pragma unroll
        for (int kb2 = 0; kb2 < 4; kb2++) {
            int j = kb2 * 2;
#pragma unroll
            for (int q = 0; q < 4; q++) {
                int jj = j + (q >> 1);
                int e0 = (q & 1) * 2;
                float p0 = sacc[jj][e0], p1 = sacc[jj][e0 + 1];
                float h0 = __bfloat162float(__float2bfloat16(p0));
                float h1 = __bfloat162float(__float2bfloat16(p1));
                PACK_BF16X2(aph[kb2][q], h1, h0);
                PACK_BF16X2(apl[kb2][q], p1 - h1, p0 - h0);
            }
        }

        // ---- O += P*V (hi/lo split, 3 passes), V via ldmatrix.trans ----
#pragma unroll
        for (int kb2 = 0; kb2 < 4; kb2++) {
#pragma unroll
            for (int ns2 = 0; ns2 < 8; ns2++) {
                uint32_t bvh[2][2], bvl[2][2];
                uint32_t vaddr = sb
                    + (uint32_t)(kb2 * 16 + (lane & 7) + ((lane >> 3) & 1) * 8) * FROWB
                    + ns2 * 32 + ((lane >> 4) & 1) * 16;
                LDMATRIX_X4_TRANS(bvh[0][0], bvh[0][1], bvh[1][0], bvh[1][1], vaddr + SVH);
                LDMATRIX_X4_TRANS(bvl[0][0], bvl[0][1], bvl[1][0], bvl[1][1], vaddr + SVL);
#pragma unroll
                for (int t = 0; t < 2; t++) {
                    int nb = ns2 * 2 + t;
                    MMA_BF16(oacc[nb], aph[kb2], bvh[t]);
                    MMA_BF16(oacc[nb], apl[kb2], bvh[t]);
                    MMA_BF16(oacc[nb], aph[kb2], bvl[t]);
                }
            }
        }
        __syncthreads();
    }

    // ---- normalize + write directly as bf16 hi/lo (fused split) ----
    const float inv0 = 1.0f / l0;
    const float inv1 = 1.0f / l1;
    const size_t obase = hbase + (size_t)(mb * 64 + warp * 16) * DMODEL;
#pragma unroll
    for (int nb = 0; nb < 16; nb++) {
        int c = nb * 8 + (lane & 3) * 2;
#pragma unroll
        for (int rr = 0; rr < 2; rr++) {
            float v0 = oacc[nb][rr*2]     * (rr ? inv1 : inv0);
            float v1 = oacc[nb][rr*2 + 1] * (rr ? inv1 : inv0);
            __nv_bfloat162 ph, pl;
            ph.x = __float2bfloat16(v0);
            ph.y = __float2bfloat16(v1);
            pl.x = __float2bfloat16(v0 - __bfloat162float(ph.x));
            pl.y = __float2bfloat16(v1 - __bfloat162float(ph.y));
            size_t off = obase + (size_t)(r0 + rr * 8) * DMODEL + c;
            *(__nv_bfloat162*)(g_ohi + off) = ph;
            *(__nv_bfloat162*)(g_olo + off) = pl;
        }
    }
}

// ---------------------------------------------------------------------------
// Launch.  Order matters for ncu (-s 5 -c 1 captures launch #6 = gemm_qkv).
// ---------------------------------------------------------------------------
extern "C" void kernel_launch(void* const* d_in, const int* in_sizes, int n_in,
                              void* d_out, int out_size) {
    const float* x  = (const float*)d_in[0];
    const float* wq = (const float*)d_in[1];
    const float* wk = (const float*)d_in[2];
    const float* wv = (const float*)d_in[3];
    const float* wo = (const float*)d_in[4];
    float* out = (float*)d_out;

    __nv_bfloat16 *xhi, *xlo;
    __nv_bfloat16 *wqhi, *wqlo, *wkhi, *wklo, *wvhi, *wvlo, *wohi, *wolo;
    cudaGetSymbolAddress((void**)&xhi, g_xhi);
    cudaGetSymbolAddress((void**)&xlo, g_xlo);
    cudaGetSymbolAddress((void**)&wqhi, g_wqhi);
    cudaGetSymbolAddress((void**)&wqlo, g_wqlo);
    cudaGetSymbolAddress((void**)&wkhi, g_wkhi);
    cudaGetSymbolAddress((void**)&wklo, g_wklo);
    cudaGetSymbolAddress((void**)&wvhi, g_wvhi);
    cudaGetSymbolAddress((void**)&wvlo, g_wvlo);
    cudaGetSymbolAddress((void**)&wohi, g_wohi);
    cudaGetSymbolAddress((void**)&wolo, g_wolo);

    const size_t nx = (size_t)BT * DMODEL;        // 16.7M
    const size_t nw = (size_t)DMODEL * DMODEL;    // 4.19M

    // Launches 1-5: splits (8 elems/thread)
    split_bf16_v8<<<(int)(nx / 2048), 256>>>(x,  xhi,  xlo,  nx);
    split_bf16_v8<<<(int)(nw / 2048), 256>>>(wq, wqhi, wqlo, nw);
    split_bf16_v8<<<(int)(nw / 2048), 256>>>(wk, wkhi, wklo, nw);
    split_bf16_v8<<<(int)(nw / 2048), 256>>>(wv, wvhi, wvlo, nw);
    split_bf16_v8<<<(int)(nw / 2048), 256>>>(wo, wohi, wolo, nw);

    // Launch 6: fused QKV (profiled by ncu)
    cudaFuncSetAttribute(gemm_qkv,
                         cudaFuncAttributeMaxDynamicSharedMemorySize, GEMM_SMEM);
    gemm_qkv<<<dim3(DMODEL / BN, BT / BM, 3), 256, GEMM_SMEM>>>();

    // Launch 7-8: RoPE table + rope/split
    rope_table_kernel<<<(SEQ * 64 + 255) / 256, 256>>>();
    {
        size_t total = (size_t)BT * NHEAD * (HDIM / 2);
        rope_split_kernel<<<(int)((total + 255) / 256), 256>>>();
    }

    // Launch 9: tensor-core flash (writes ohi/olo directly)
    cudaFuncSetAttribute(flash_attn_tc,
                         cudaFuncAttributeMaxDynamicSharedMemorySize, FA_SMEM);
    flash_attn_tc<<<dim3(SEQ / 64, BATCH * NHEAD), 128, FA_SMEM>>>();

    // Launch 10: output projection
    cudaFuncSetAttribute(gemm_out,
                         cudaFuncAttributeMaxDynamicSharedMemorySize, GEMM_SMEM);
    gemm_out<<<dim3(DMODEL / BN, BT / BM, 1), 256, GEMM_SMEM>>>(out);
}

// round 12
// speedup vs baseline: 3.0942x; 1.0203x over previous
#include <cuda_runtime.h>
#include <cuda_bf16.h>
#include <math.h>
#include <stdint.h>

// ---------------------------------------------------------------------------
// Problem constants
// ---------------------------------------------------------------------------
#define BATCH   4
#define SEQ     2048
#define DMODEL  2048
#define NHEAD   16
#define HDIM    128
#define BT      (BATCH * SEQ)   // 8192

__device__ __forceinline__ uint32_t smem_to_u32(const void* smem_ptr) {
    uint32_t addr;
    asm("{ .reg .u64 tmp; cvta.to.shared.u64 tmp, %1; cvt.u32.u64 %0, tmp; }"
        : "=r"(addr) : "l"(smem_ptr));
    return addr;
}

#define CP_ASYNC_16(dst_u32, src_ptr) \
    asm volatile("cp.async.cg.shared.global [%0], [%1], 16;" \
        :: "r"(dst_u32), "l"(src_ptr) : "memory")
#define CP_ASYNC_COMMIT() asm volatile("cp.async.commit_group;" ::: "memory")
#define CP_ASYNC_WAIT_1() asm volatile("cp.async.wait_group 1;" ::: "memory")
#define CP_ASYNC_WAIT_0() asm volatile("cp.async.wait_group 0;" ::: "memory")

#define LDMATRIX_X4(r0, r1, r2, r3, addr) \
    asm volatile("ldmatrix.sync.aligned.m8n8.x4.shared.b16 {%0,%1,%2,%3}, [%4];" \
        : "=r"(r0), "=r"(r1), "=r"(r2), "=r"(r3) : "r"(addr))

#define LDMATRIX_X4_TRANS(r0, r1, r2, r3, addr) \
    asm volatile("ldmatrix.sync.aligned.m8n8.x4.trans.shared.b16 {%0,%1,%2,%3}, [%4];" \
        : "=r"(r0), "=r"(r1), "=r"(r2), "=r"(r3) : "r"(addr))

#define MMA_BF16(c, a, b) \
    asm volatile( \
        "mma.sync.aligned.m16n8k16.row.col.f32.bf16.bf16.f32 " \
        "{%0,%1,%2,%3}, {%4,%5,%6,%7}, {%8,%9}, {%0,%1,%2,%3};" \
        : "+f"((c)[0]), "+f"((c)[1]), "+f"((c)[2]), "+f"((c)[3]) \
        : "r"((a)[0]), "r"((a)[1]), "r"((a)[2]), "r"((a)[3]), \
          "r"((b)[0]), "r"((b)[1]))

#define PACK_BF16X2(d, hi_f, lo_f) \
    asm("cvt.rn.bf16x2.f32 %0, %1, %2;" : "=r"(d) : "f"(hi_f), "f"(lo_f))

// ---------------------------------------------------------------------------
// Scratch (allocation-free rule: __device__ globals)
// ---------------------------------------------------------------------------
__device__ float g_q[(size_t)BT * DMODEL];
__device__ float g_k[(size_t)BT * DMODEL];
__device__ float2 g_rope_tab[SEQ * 64];

__device__ __nv_bfloat16 g_xhi[(size_t)BT * DMODEL];
__device__ __nv_bfloat16 g_xlo[(size_t)BT * DMODEL];
__device__ __nv_bfloat16 g_ohi[(size_t)BT * DMODEL];
__device__ __nv_bfloat16 g_olo[(size_t)BT * DMODEL];
__device__ __nv_bfloat16 g_wqhi[(size_t)DMODEL * DMODEL];
__device__ __nv_bfloat16 g_wqlo[(size_t)DMODEL * DMODEL];
__device__ __nv_bfloat16 g_wkhi[(size_t)DMODEL * DMODEL];
__device__ __nv_bfloat16 g_wklo[(size_t)DMODEL * DMODEL];
__device__ __nv_bfloat16 g_wvhi[(size_t)DMODEL * DMODEL];
__device__ __nv_bfloat16 g_wvlo[(size_t)DMODEL * DMODEL];
__device__ __nv_bfloat16 g_wohi[(size_t)DMODEL * DMODEL];
__device__ __nv_bfloat16 g_wolo[(size_t)DMODEL * DMODEL];

__device__ __nv_bfloat16 g_qhi[(size_t)BT * DMODEL];
__device__ __nv_bfloat16 g_qlo[(size_t)BT * DMODEL];
__device__ __nv_bfloat16 g_khi[(size_t)BT * DMODEL];
__device__ __nv_bfloat16 g_klo[(size_t)BT * DMODEL];
__device__ __nv_bfloat16 g_vhi[(size_t)BT * DMODEL];
__device__ __nv_bfloat16 g_vlo[(size_t)BT * DMODEL];

// ---------------------------------------------------------------------------
// Vectorized fp32 -> (bf16 hi, bf16 lo) split: 8 elems/thread
// ---------------------------------------------------------------------------
__global__ __launch_bounds__(256)
void split_bf16_v8(const float* __restrict__ src,
                   __nv_bfloat16* __restrict__ hi, __nv_bfloat16* __restrict__ lo,
                   size_t n) {
    size_t i8 = ((size_t)blockIdx.x * 256 + threadIdx.x) * 8;
    if (i8 >= n) return;
    float4 a = *(const float4*)(src + i8);
    float4 b = *(const float4*)(src + i8 + 4);
    float v[8] = {a.x, a.y, a.z, a.w, b.x, b.y, b.z, b.w};
    __nv_bfloat162 ph[4], pl[4];
#pragma unroll
    for (int j = 0; j < 4; j++) {
        __nv_bfloat16 h0 = __float2bfloat16(v[2*j]);
        __nv_bfloat16 h1 = __float2bfloat16(v[2*j+1]);
        ph[j].x = h0; ph[j].y = h1;
        pl[j].x = __float2bfloat16(v[2*j]   - __bfloat162float(h0));
        pl[j].y = __float2bfloat16(v[2*j+1] - __bfloat162float(h1));
    }
    *(uint4*)(hi + i8) = *(uint4*)ph;
    *(uint4*)(lo + i8) = *(uint4*)pl;
}

// ---------------------------------------------------------------------------
// RoPE table in double precision (immune to --use_fast_math)
// ---------------------------------------------------------------------------
__global__ __launch_bounds__(256)
void rope_table_kernel() {
    int idx = blockIdx.x * blockDim.x + threadIdx.x;
    if (idx >= SEQ * 64) return;
    int i = idx & 63;
    int t = idx >> 6;
    float inv_freq = (float)exp(-log(10000.0) * ((double)i / 64.0));
    float ang_f = (float)t * inv_freq;
    double ang = (double)ang_f;
    g_rope_tab[idx] = make_float2((float)cos(ang), (float)sin(ang));
}

// ---------------------------------------------------------------------------
// RoPE + bf16 hi/lo split for q and k (fused)
// ---------------------------------------------------------------------------
__global__ __launch_bounds__(256)
void rope_split_kernel() {
    const size_t total = (size_t)BT * NHEAD * (HDIM / 2);
    size_t idx = (size_t)blockIdx.x * blockDim.x + threadIdx.x;
    if (idx >= total) return;

    int i  = (int)(idx & 63);
    int h  = (int)((idx >> 6) & (NHEAD - 1));
    int bt = (int)(idx >> 10);
    int t  = bt & (SEQ - 1);

    float2 cs = g_rope_tab[t * 64 + i];
    float c = cs.x, s = cs.y;

    size_t base = (size_t)bt * DMODEL + h * HDIM + i;

    float q1 = g_q[base], q2 = g_q[base + 64];
    float qa = q1 * c - q2 * s;
    float qb = q2 * c + q1 * s;
    __nv_bfloat16 qah = __float2bfloat16(qa);
    __nv_bfloat16 qbh = __float2bfloat16(qb);
    g_qhi[base]      = qah; g_qlo[base]      = __float2bfloat16(qa - __bfloat162float(qah));
    g_qhi[base + 64] = qbh; g_qlo[base + 64] = __float2bfloat16(qb - __bfloat162float(qbh));

    float k1 = g_k[base], k2 = g_k[base + 64];
    float ka = k1 * c - k2 * s;
    float kb = k2 * c + k1 * s;
    __nv_bfloat16 kah = __float2bfloat16(ka);
    __nv_bfloat16 kbh = __float2bfloat16(kb);
    g_khi[base]      = kah; g_klo[base]      = __float2bfloat16(ka - __bfloat162float(kah));
    g_khi[base + 64] = kbh; g_klo[base + 64] = __float2bfloat16(kb - __bfloat162float(kbh));
}

// ---------------------------------------------------------------------------
// bf16-split GEMM, 3-stage cp.async pipeline, ONE __syncthreads per K-iter.
// Safety: at iter kt the top sync joins all warps after iter kt-1's MMAs
// (last readers of buffer (kt-1)%3); the prefetch of stage kt+2 then writes
// that same buffer race-free while iter kt's MMAs read buffer kt%3.
// ---------------------------------------------------------------------------
#define BM 128
#define BN 128
#define BK 32
#define ROWB 80
#define TILE_B (128 * ROWB)
#define STAGE_B (4 * TILE_B)          // 40960 B
#define GEMM_SMEM (3 * STAGE_B)       // 122880 B

__device__ __forceinline__
void gemm_body(const __nv_bfloat16* __restrict__ Ahi,
               const __nv_bfloat16* __restrict__ Alo,
               const __nv_bfloat16* __restrict__ Bhi,
               const __nv_bfloat16* __restrict__ Blo,
               float* __restrict__ Cf,
               __nv_bfloat16* __restrict__ Chi,
               __nv_bfloat16* __restrict__ Clo,
               int N, int K, char* smem) {
    const uint32_t sb = smem_to_u32(smem);
    const int tid  = threadIdx.x;
    const int lane = tid & 31;
    const int wid  = tid >> 5;
    const int warp_m = wid & 1;
    const int warp_n = wid >> 1;

    const int row0 = blockIdx.y * BM;
    const int col0 = blockIdx.x * BN;

    float acc[4][4][4];
#pragma unroll
    for (int mi = 0; mi < 4; mi++)
#pragma unroll
        for (int ni = 0; ni < 4; ni++)
#pragma unroll
            for (int e = 0; e < 4; e++) acc[mi][ni][e] = 0.f;

    const int r_ld  = tid >> 2;
    const int c_ld  = (tid & 3) * 16;
    const int ke_ld = (tid & 3) * 8;

    // ---- prologue: stages 0 and 1 ----
#pragma unroll
    for (int s = 0; s < 2; s++) {
        const int k0 = s * BK;
        const uint32_t base = sb + s * STAGE_B;
#pragma unroll
        for (int half = 0; half < 2; half++) {
            int r = r_ld + half * 64;
            uint32_t d = base + r * ROWB + c_ld;
            size_t ga = (size_t)(row0 + r) * K + k0 + ke_ld;
            size_t gb = (size_t)(col0 + r) * K + k0 + ke_ld;
            CP_ASYNC_16(d + 0 * TILE_B, Ahi + ga);
            CP_ASYNC_16(d + 1 * TILE_B, Alo + ga);
            CP_ASYNC_16(d + 2 * TILE_B, Bhi + gb);
            CP_ASYNC_16(d + 3 * TILE_B, Blo + gb);
        }
        CP_ASYNC_COMMIT();
    }

    const int niter = K / BK;
    int stage = 0;                     // kt % 3
    for (int kt = 0; kt < niter; kt++) {
        CP_ASYNC_WAIT_1();             // stage kt resident (kt+1 may be in flight)
        __syncthreads();               // all warps done reading buffer (kt-1)%3

        // prefetch stage kt+2 into buffer (kt+2)%3 == (kt-1)%3 — overlaps MMAs
        {
            int pstage = stage + 2; if (pstage >= 3) pstage -= 3;
            if (kt + 2 < niter) {
                const int k0 = (kt + 2) * BK;
                const uint32_t base = sb + pstage * STAGE_B;
#pragma unroll
                for (int half = 0; half < 2; half++) {
                    int r = r_ld + half * 64;
                    uint32_t d = base + r * ROWB + c_ld;
                    size_t ga = (size_t)(row0 + r) * K + k0 + ke_ld;
                    size_t gb = (size_t)(col0 + r) * K + k0 + ke_ld;
                    CP_ASYNC_16(d + 0 * TILE_B, Ahi + ga);
                    CP_ASYNC_16(d + 1 * TILE_B, Alo + ga);
                    CP_ASYNC_16(d + 2 * TILE_B, Bhi + gb);
                    CP_ASYNC_16(d + 3 * TILE_B, Blo + gb);
                }
            }
            CP_ASYNC_COMMIT();         // one group per iter (possibly empty)
        }

        const uint32_t base  = sb + stage * STAGE_B;
        const uint32_t a_hiB = base + 0 * TILE_B;
        const uint32_t a_loB = base + 1 * TILE_B;
        const uint32_t b_hiB = base + 2 * TILE_B;
        const uint32_t b_loB = base + 3 * TILE_B;

#pragma unroll
        for (int ks = 0; ks < 2; ks++) {
            const int kb = ks * 32;

            uint32_t ah[4][4], al[4][4], bh[4][2], bl[4][2];
            const int ar = warp_m * 64 + (lane & 15);
            const uint32_t acol = kb + ((lane >> 4) << 4);
#pragma unroll
            for (int mi = 0; mi < 4; mi++) {
                uint32_t off = (uint32_t)(ar + mi * 16) * ROWB + acol;
                LDMATRIX_X4(ah[mi][0], ah[mi][1], ah[mi][2], ah[mi][3], a_hiB + off);
                LDMATRIX_X4(al[mi][0], al[mi][1], al[mi][2], al[mi][3], a_loB + off);
            }
            const int brr = warp_n * 32 + ((lane >> 4) & 1) * 8 + (lane & 7);
            const uint32_t bcol = kb + ((lane >> 3) & 1) * 16;
#pragma unroll
            for (int nb = 0; nb < 2; nb++) {
                uint32_t off = (uint32_t)(brr + nb * 16) * ROWB + bcol;
                LDMATRIX_X4(bh[2*nb][0], bh[2*nb][1], bh[2*nb+1][0], bh[2*nb+1][1],
                            b_hiB + off);
                LDMATRIX_X4(bl[2*nb][0], bl[2*nb][1], bl[2*nb+1][0], bl[2*nb+1][1],
                            b_loB + off);
            }
#pragma unroll
            for (int mi = 0; mi < 4; mi++)
#pragma unroll
                for (int ni = 0; ni < 4; ni++) {
                    MMA_BF16(acc[mi][ni], ah[mi], bh[ni]);
                    MMA_BF16(acc[mi][ni], ah[mi], bl[ni]);
                    MMA_BF16(acc[mi][ni], al[mi], bh[ni]);
                }
        }

        if (++stage >= 3) stage = 0;
    }

    // ---- epilogue (no smem use; no sync needed) ----
#pragma unroll
    for (int mi = 0; mi < 4; mi++) {
        int r = row0 + warp_m * 64 + mi * 16 + (lane >> 2);
#pragma unroll
        for (int ni = 0; ni < 4; ni++) {
            int c = col0 + warp_n * 32 + ni * 8 + (lane & 3) * 2;
            if (Cf) {
                *(float2*)(Cf + (size_t)r * N + c) =
                    make_float2(acc[mi][ni][0], acc[mi][ni][1]);
                *(float2*)(Cf + (size_t)(r + 8) * N + c) =
                    make_float2(acc[mi][ni][2], acc[mi][ni][3]);
            } else {
#pragma unroll
                for (int rr = 0; rr < 2; rr++) {
                    float v0 = acc[mi][ni][rr*2], v1 = acc[mi][ni][rr*2+1];
                    __nv_bfloat162 ph, pl;
                    ph.x = __float2bfloat16(v0);
                    ph.y = __float2bfloat16(v1);
                    pl.x = __float2bfloat16(v0 - __bfloat162float(ph.x));
                    pl.y = __float2bfloat16(v1 - __bfloat162float(ph.y));
                    size_t off = (size_t)(r + rr * 8) * N + c;
                    *(__nv_bfloat162*)(Chi + off) = ph;
                    *(__nv_bfloat162*)(Clo + off) = pl;
                }
            }
        }
    }
}

// Fused QKV: z selects weight set; z=2 (V) writes bf16 hi/lo directly.
__global__ __launch_bounds__(256, 1)
void gemm_qkv() {
    extern __shared__ char smem[];
    const int z = blockIdx.z;
    if (z == 0)
        gemm_body(g_xhi, g_xlo, g_wqhi, g_wqlo, g_q, nullptr, nullptr,
                  DMODEL, DMODEL, smem);
    else if (z == 1)
        gemm_body(g_xhi, g_xlo, g_wkhi, g_wklo, g_k, nullptr, nullptr,
                  DMODEL, DMODEL, smem);
    else
        gemm_body(g_xhi, g_xlo, g_wvhi, g_wvlo, nullptr, g_vhi, g_vlo,
                  DMODEL, DMODEL, smem);
}

// Output projection: reads ohi/olo (written by flash) and wo, writes fp32 out.
__global__ __launch_bounds__(256, 1)
void gemm_out(float* __restrict__ out) {
    extern __shared__ char smem[];
    gemm_body(g_ohi, g_olo, g_wohi, g_wolo, out, nullptr, nullptr,
              DMODEL, DMODEL, smem);
}

// ---------------------------------------------------------------------------
// Tensor-core flash attention (causal, bf16 hi/lo split, fp32 accum).
// Writes O directly as bf16 hi/lo (fused split for the output projection).
// ---------------------------------------------------------------------------
#define FROWB 272
#define FTILE (64 * FROWB)
#define SQH 0
#define SQL (1 * FTILE)
#define SKH (2 * FTILE)
#define SKL (3 * FTILE)
#define SVH (4 * FTILE)
#define SVL (5 * FTILE)
#define FA_SMEM (6 * FTILE)      // 104448 B

__global__ __launch_bounds__(128)
void flash_attn_tc() {
    extern __shared__ char sm[];
    const uint32_t sb = smem_to_u32(sm);
    const int tid  = threadIdx.x;
    const int lane = tid & 31;
    const int warp = tid >> 5;

    const int mb = (int)gridDim.x - 1 - (int)blockIdx.x;  // heavy tiles first
    const int bh = blockIdx.y;
    const int b  = bh >> 4;
    const int h  = bh & 15;
    const float scale = 0.08838834764831845f;

    const size_t hbase = (size_t)b * SEQ * DMODEL + (size_t)h * HDIM;

    // ---- load Q tile (hi+lo): 64 rows x 256B = 1024 x 16B chunks ----
    {
        const size_t q0 = hbase + (size_t)mb * 64 * DMODEL;
        for (int i = tid; i < 1024; i += 128) {
            int r = i >> 4, c = i & 15;
            uint32_t d = sb + r * FROWB + c * 16;
            size_t g = q0 + (size_t)r * DMODEL + c * 8;
            CP_ASYNC_16(d + SQH, g_qhi + g);
            CP_ASYNC_16(d + SQL, g_qlo + g);
        }
        CP_ASYNC_COMMIT();
    }

    const int r0 = lane >> 2;
    float m0 = -INFINITY, m1 = -INFINITY, l0 = 0.f, l1 = 0.f;
    float oacc[16][4];
#pragma unroll
    for (int nb = 0; nb < 16; nb++)
#pragma unroll
        for (int e = 0; e < 4; e++) oacc[nb][e] = 0.f;

    for (int jb = 0; jb <= mb; jb++) {
        {
            const size_t kv0 = hbase + (size_t)jb * 64 * DMODEL;
            for (int i = tid; i < 1024; i += 128) {
                int r = i >> 4, c = i & 15;
                uint32_t d = sb + r * FROWB + c * 16;
                size_t g = kv0 + (size_t)r * DMODEL + c * 8;
                CP_ASYNC_16(d + SKH, g_khi + g);
                CP_ASYNC_16(d + SKL, g_klo + g);
                CP_ASYNC_16(d + SVH, g_vhi + g);
                CP_ASYNC_16(d + SVL, g_vlo + g);
            }
            CP_ASYNC_COMMIT();
            CP_ASYNC_WAIT_0();
            __syncthreads();
        }

        // ---- S = Q*K^T (hi/lo split, 3 passes) ----
        float sacc[8][4];
#pragma unroll
        for (int j = 0; j < 8; j++)
#pragma unroll
            for (int e = 0; e < 4; e++) sacc[j][e] = 0.f;

#pragma unroll
        for (int ks = 0; ks < 8; ks++) {
            const int kb = ks * 32;
            uint32_t aqh[4], aql[4];
            uint32_t aaddr = sb + (uint32_t)(warp * 16 + (lane & 15)) * FROWB
                           + kb + ((lane >> 4) << 4);
            LDMATRIX_X4(aqh[0], aqh[1], aqh[2], aqh[3], aaddr + SQH);
            LDMATRIX_X4(aql[0], aql[1], aql[2], aql[3], aaddr + SQL);
#pragma unroll
            for (int nsl = 0; nsl < 4; nsl++) {
                uint32_t bkh[2][2], bkl[2][2];
                uint32_t baddr = sb
                    + (uint32_t)(nsl * 16 + ((lane >> 4) & 1) * 8 + (lane & 7)) * FROWB
                    + kb + ((lane >> 3) & 1) * 16;
                LDMATRIX_X4(bkh[0][0], bkh[0][1], bkh[1][0], bkh[1][1], baddr + SKH);
                LDMATRIX_X4(bkl[0][0], bkl[0][1], bkl[1][0], bkl[1][1], baddr + SKL);
#pragma unroll
                for (int t = 0; t < 2; t++) {
                    int j = nsl * 2 + t;
                    MMA_BF16(sacc[j], aqh, bkh[t]);
                    MMA_BF16(sacc[j], aqh, bkl[t]);
                    MMA_BF16(sacc[j], aql, bkh[t]);
                }
            }
        }

#pragma unroll
        for (int j = 0; j < 8; j++)
#pragma unroll
            for (int e = 0; e < 4; e++) sacc[j][e] *= scale;

        if (jb == mb) {
            const int row0 = warp * 16 + r0;
            const int row1 = row0 + 8;
#pragma unroll
            for (int j = 0; j < 8; j++) {
                int c0 = j * 8 + (lane & 3) * 2;
                if (c0     > row0) sacc[j][0] = -INFINITY;
                if (c0 + 1 > row0) sacc[j][1] = -INFINITY;
                if (c0     > row1) sacc[j][2] = -INFINITY;
                if (c0 + 1 > row1) sacc[j][3] = -INFINITY;
            }
        }

        // ---- online softmax ----
        float mn0 = -INFINITY, mn1 = -INFINITY;
#pragma unroll
        for (int j = 0; j < 8; j++) {
            mn0 = fmaxf(mn0, fmaxf(sacc[j][0], sacc[j][1]));
            mn1 = fmaxf(mn1, fmaxf(sacc[j][2], sacc[j][3]));
        }
        mn0 = fmaxf(mn0, __shfl_xor_sync(0xffffffffu, mn0, 1));
        mn0 = fmaxf(mn0, __shfl_xor_sync(0xffffffffu, mn0, 2));
        mn1 = fmaxf(mn1, __shfl_xor_sync(0xffffffffu, mn1, 1));
        mn1 = fmaxf(mn1, __shfl_xor_sync(0xffffffffu, mn1, 2));
        mn0 = fmaxf(mn0, m0);
        mn1 = fmaxf(mn1, m1);

        float alpha0 = __expf(m0 - mn0);
        float alpha1 = __expf(m1 - mn1);
        m0 = mn0; m1 = mn1;
        l0 *= alpha0; l1 *= alpha1;
#pragma unroll
        for (int nb = 0; nb < 16; nb++) {
            oacc[nb][0] *= alpha0; oacc[nb][1] *= alpha0;
            oacc[nb][2] *= alpha1; oacc[nb][3] *= alpha1;
        }

        float rs0 = 0.f, rs1 = 0.f;
#pragma unroll
        for (int j = 0; j < 8; j++) {
            float p0 = __expf(sacc[j][0] - mn0);
            float p1 = __expf(sacc[j][1] - mn0);
            float p2 = __expf(sacc[j][2] - mn1);
            float p3 = __expf(sacc[j][3] - mn1);
            sacc[j][0] = p0; sacc[j][1] = p1; sacc[j][2] = p2; sacc[j][3] = p3;
            rs0 += p0 + p1; rs1 += p2 + p3;
        }
        rs0 += __shfl_xor_sync(0xffffffffu, rs0, 1);
        rs0 += __shfl_xor_sync(0xffffffffu, rs0, 2);
        rs1 += __shfl_xor_sync(0xffffffffu, rs1, 1);
        rs1 += __shfl_xor_sync(0xffffffffu, rs1, 2);
        l0 += rs0; l1 += rs1;

        // ---- P fragments (hi/lo) directly from S accumulators ----
        uint32_t aph[4][4], apl[4][4];
#pragma unroll
        for (int kb2 = 0; kb2 < 4; kb2++) {
            int j = kb2 * 2;
#pragma unroll
            for (int q = 0; q < 4; q++) {
                int jj = j + (q >> 1);
                int e0 = (q & 1) * 2;
                float p0 = sacc[jj][e0], p1 = sacc[jj][e0 + 1];
                float h0 = __bfloat162float(__float2bfloat16(p0));
                float h1 = __bfloat162float(__float2bfloat16(p1));
                PACK_BF16X2(aph[kb2][q], h1, h0);
                PACK_BF16X2(apl[kb2][q], p1 - h1, p0 - h0);
            }
        }

        // ---- O += P*V (hi/lo split, 3 passes), V via ldmatrix.trans ----
#pragma unroll
        for (int kb2 = 0; kb2 < 4; kb2++) {
#pragma unroll
            for (int ns2 = 0; ns2 < 8; ns2++) {
                uint32_t bvh[2][2], bvl[2][2];
                uint32_t vaddr = sb
                    + (uint32_t)(kb2 * 16 + (lane & 7) + ((lane >> 3) & 1) * 8) * FROWB
                    + ns2 * 32 + ((lane >> 4) & 1) * 16;
                LDMATRIX_X4_TRANS(bvh[0][0], bvh[0][1], bvh[1][0], bvh[1][1], vaddr + SVH);
                LDMATRIX_X4_TRANS(bvl[0][0], bvl[0][1], bvl[1][0], bvl[1][1], vaddr + SVL);
#pragma unroll
                for (int t = 0; t < 2; t++) {
                    int nb = ns2 * 2 + t;
                    MMA_BF16(oacc[nb], aph[kb2], bvh[t]);
                    MMA_BF16(oacc[nb], apl[kb2], bvh[t]);
                    MMA_BF16(oacc[nb], aph[kb2], bvl[t]);
                }
            }
        }
        __syncthreads();   // smem K/V reused next iteration
    }

    // ---- normalize + write directly as bf16 hi/lo (fused split) ----
    const float inv0 = 1.0f / l0;
    const float inv1 = 1.0f / l1;
    const size_t obase = hbase + (size_t)(mb * 64 + warp * 16) * DMODEL;
#pragma unroll
    for (int nb = 0; nb < 16; nb++) {
        int c = nb * 8 + (lane & 3) * 2;
#pragma unroll
        for (int rr = 0; rr < 2; rr++) {
            float v0 = oacc[nb][rr*2]     * (rr ? inv1 : inv0);
            float v1 = oacc[nb][rr*2 + 1] * (rr ? inv1 : inv0);
            __nv_bfloat162 ph, pl;
            ph.x = __float2bfloat16(v0);
            ph.y = __float2bfloat16(v1);
            pl.x = __float2bfloat16(v0 - __bfloat162float(ph.x));
            pl.y = __float2bfloat16(v1 - __bfloat162float(ph.y));
            size_t off = obase + (size_t)(r0 + rr * 8) * DMODEL + c;
            *(__nv_bfloat162*)(g_ohi + off) = ph;
            *(__nv_bfloat162*)(g_olo + off) = pl;
        }
    }
}

// ---------------------------------------------------------------------------
// Launch
// ---------------------------------------------------------------------------
extern "C" void kernel_launch(void* const* d_in, const int* in_sizes, int n_in,
                              void* d_out, int out_size) {
    const float* x  = (const float*)d_in[0];
    const float* wq = (const float*)d_in[1];
    const float* wk = (const float*)d_in[2];
    const float* wv = (const float*)d_in[3];
    const float* wo = (const float*)d_in[4];
    float* out = (float*)d_out;

    __nv_bfloat16 *xhi, *xlo;
    __nv_bfloat16 *wqhi, *wqlo, *wkhi, *wklo, *wvhi, *wvlo, *wohi, *wolo;
    cudaGetSymbolAddress((void**)&xhi, g_xhi);
    cudaGetSymbolAddress((void**)&xlo, g_xlo);
    cudaGetSymbolAddress((void**)&wqhi, g_wqhi);
    cudaGetSymbolAddress((void**)&wqlo, g_wqlo);
    cudaGetSymbolAddress((void**)&wkhi, g_wkhi);
    cudaGetSymbolAddress((void**)&wklo, g_wklo);
    cudaGetSymbolAddress((void**)&wvhi, g_wvhi);
    cudaGetSymbolAddress((void**)&wvlo, g_wvlo);
    cudaGetSymbolAddress((void**)&wohi, g_wohi);
    cudaGetSymbolAddress((void**)&wolo, g_wolo);

    const size_t nx = (size_t)BT * DMODEL;        // 16.7M
    const size_t nw = (size_t)DMODEL * DMODEL;    // 4.19M

    // Splits (8 elems/thread)
    split_bf16_v8<<<(int)(nx / 2048), 256>>>(x,  xhi,  xlo,  nx);
    split_bf16_v8<<<(int)(nw / 2048), 256>>>(wq, wqhi, wqlo, nw);
    split_bf16_v8<<<(int)(nw / 2048), 256>>>(wk, wkhi, wklo, nw);
    split_bf16_v8<<<(int)(nw / 2048), 256>>>(wv, wvhi, wvlo, nw);
    split_bf16_v8<<<(int)(nw / 2048), 256>>>(wo, wohi, wolo, nw);

    // Fused QKV (3-stage pipeline)
    cudaFuncSetAttribute(gemm_qkv,
                         cudaFuncAttributeMaxDynamicSharedMemorySize, GEMM_SMEM);
    gemm_qkv<<<dim3(DMODEL / BN, BT / BM, 3), 256, GEMM_SMEM>>>();

    // RoPE table + rope/split
    rope_table_kernel<<<(SEQ * 64 + 255) / 256, 256>>>();
    {
        size_t total = (size_t)BT * NHEAD * (HDIM / 2);
        rope_split_kernel<<<(int)((total + 255) / 256), 256>>>();
    }

    // Tensor-core flash (writes ohi/olo directly)
    cudaFuncSetAttribute(flash_attn_tc,
                         cudaFuncAttributeMaxDynamicSharedMemorySize, FA_SMEM);
    flash_attn_tc<<<dim3(SEQ / 64, BATCH * NHEAD), 128, FA_SMEM>>>();

    // Output projection
    cudaFuncSetAttribute(gemm_out,
                         cudaFuncAttributeMaxDynamicSharedMemorySize, GEMM_SMEM);
    gemm_out<<<dim3(DMODEL / BN, BT / BM, 1), 256, GEMM_SMEM>>>(out);
}

// round 14
// speedup vs baseline: 3.4373x; 1.1109x over previous
#include <cuda_runtime.h>
#include <cuda_bf16.h>
#include <math.h>
#include <stdint.h>

// ---------------------------------------------------------------------------
// Problem constants
// ---------------------------------------------------------------------------
#define BATCH   4
#define SEQ     2048
#define DMODEL  2048
#define NHEAD   16
#define HDIM    128
#define BT      (BATCH * SEQ)   // 8192

__device__ __forceinline__ uint32_t smem_to_u32(const void* smem_ptr) {
    uint32_t addr;
    asm("{ .reg .u64 tmp; cvta.to.shared.u64 tmp, %1; cvt.u32.u64 %0, tmp; }"
        : "=r"(addr) : "l"(smem_ptr));
    return addr;
}

#define CP_ASYNC_16(dst_u32, src_ptr) \
    asm volatile("cp.async.cg.shared.global [%0], [%1], 16;" \
        :: "r"(dst_u32), "l"(src_ptr) : "memory")
#define CP_ASYNC_COMMIT() asm volatile("cp.async.commit_group;" ::: "memory")
#define CP_ASYNC_WAIT_1() asm volatile("cp.async.wait_group 1;" ::: "memory")
#define CP_ASYNC_WAIT_0() asm volatile("cp.async.wait_group 0;" ::: "memory")

#define LDMATRIX_X4(r0, r1, r2, r3, addr) \
    asm volatile("ldmatrix.sync.aligned.m8n8.x4.shared.b16 {%0,%1,%2,%3}, [%4];" \
        : "=r"(r0), "=r"(r1), "=r"(r2), "=r"(r3) : "r"(addr))

#define LDMATRIX_X4_TRANS(r0, r1, r2, r3, addr) \
    asm volatile("ldmatrix.sync.aligned.m8n8.x4.trans.shared.b16 {%0,%1,%2,%3}, [%4];" \
        : "=r"(r0), "=r"(r1), "=r"(r2), "=r"(r3) : "r"(addr))

#define MMA_BF16(c, a, b) \
    asm volatile( \
        "mma.sync.aligned.m16n8k16.row.col.f32.bf16.bf16.f32 " \
        "{%0,%1,%2,%3}, {%4,%5,%6,%7}, {%8,%9}, {%0,%1,%2,%3};" \
        : "+f"((c)[0]), "+f"((c)[1]), "+f"((c)[2]), "+f"((c)[3]) \
        : "r"((a)[0]), "r"((a)[1]), "r"((a)[2]), "r"((a)[3]), \
          "r"((b)[0]), "r"((b)[1]))

#define PACK_BF16X2(d, hi_f, lo_f) \
    asm("cvt.rn.bf16x2.f32 %0, %1, %2;" : "=r"(d) : "f"(hi_f), "f"(lo_f))

// ---------------------------------------------------------------------------
// Scratch (allocation-free rule: __device__ globals)
// ---------------------------------------------------------------------------
__device__ float g_q[(size_t)BT * DMODEL];
__device__ float g_k[(size_t)BT * DMODEL];
__device__ float2 g_rope_tab[SEQ * 64];

__device__ __nv_bfloat16 g_xhi[(size_t)BT * DMODEL];
__device__ __nv_bfloat16 g_xlo[(size_t)BT * DMODEL];
__device__ __nv_bfloat16 g_ohi[(size_t)BT * DMODEL];
__device__ __nv_bfloat16 g_olo[(size_t)BT * DMODEL];
__device__ __nv_bfloat16 g_wqhi[(size_t)DMODEL * DMODEL];
__device__ __nv_bfloat16 g_wqlo[(size_t)DMODEL * DMODEL];
__device__ __nv_bfloat16 g_wkhi[(size_t)DMODEL * DMODEL];
__device__ __nv_bfloat16 g_wklo[(size_t)DMODEL * DMODEL];
__device__ __nv_bfloat16 g_wvhi[(size_t)DMODEL * DMODEL];
__device__ __nv_bfloat16 g_wvlo[(size_t)DMODEL * DMODEL];
__device__ __nv_bfloat16 g_wohi[(size_t)DMODEL * DMODEL];
__device__ __nv_bfloat16 g_wolo[(size_t)DMODEL * DMODEL];

__device__ __nv_bfloat16 g_qhi[(size_t)BT * DMODEL];
__device__ __nv_bfloat16 g_qlo[(size_t)BT * DMODEL];
__device__ __nv_bfloat16 g_khi[(size_t)BT * DMODEL];
__device__ __nv_bfloat16 g_klo[(size_t)BT * DMODEL];
__device__ __nv_bfloat16 g_vhi[(size_t)BT * DMODEL];
__device__ __nv_bfloat16 g_vlo[(size_t)BT * DMODEL];

// ---------------------------------------------------------------------------
// Vectorized fp32 -> (bf16 hi, bf16 lo) split: 8 elems/thread
// ---------------------------------------------------------------------------
__device__ __forceinline__
void split8(const float* __restrict__ src,
            __nv_bfloat16* __restrict__ hi, __nv_bfloat16* __restrict__ lo,
            size_t i8) {
    float4 a = *(const float4*)(src + i8);
    float4 b = *(const float4*)(src + i8 + 4);
    float v[8] = {a.x, a.y, a.z, a.w, b.x, b.y, b.z, b.w};
    __nv_bfloat162 ph[4], pl[4];
#pragma unroll
    for (int j = 0; j < 4; j++) {
        __nv_bfloat16 h0 = __float2bfloat16(v[2*j]);
        __nv_bfloat16 h1 = __float2bfloat16(v[2*j+1]);
        ph[j].x = h0; ph[j].y = h1;
        pl[j].x = __float2bfloat16(v[2*j]   - __bfloat162float(h0));
        pl[j].y = __float2bfloat16(v[2*j+1] - __bfloat162float(h1));
    }
    *(uint4*)(hi + i8) = *(uint4*)ph;
    *(uint4*)(lo + i8) = *(uint4*)pl;
}

__global__ __launch_bounds__(256)
void split_bf16_v8(const float* __restrict__ src,
                   __nv_bfloat16* __restrict__ hi, __nv_bfloat16* __restrict__ lo,
                   size_t n) {
    size_t i8 = ((size_t)blockIdx.x * 256 + threadIdx.x) * 8;
    if (i8 >= n) return;
    split8(src, hi, lo, i8);
}

// Fused weight splits: blockIdx.y selects which weight (0=q,1=k,2=v,3=o).
__global__ __launch_bounds__(256)
void split_weights(const float* __restrict__ wq, const float* __restrict__ wk,
                   const float* __restrict__ wv, const float* __restrict__ wo) {
    const size_t nw = (size_t)DMODEL * DMODEL;
    size_t i8 = ((size_t)blockIdx.x * 256 + threadIdx.x) * 8;
    if (i8 >= nw) return;
    switch (blockIdx.y) {
        case 0: split8(wq, g_wqhi, g_wqlo, i8); break;
        case 1: split8(wk, g_wkhi, g_wklo, i8); break;
        case 2: split8(wv, g_wvhi, g_wvlo, i8); break;
        default: split8(wo, g_wohi, g_wolo, i8); break;
    }
}

// ---------------------------------------------------------------------------
// RoPE table in double precision (immune to --use_fast_math)
// ---------------------------------------------------------------------------
__global__ __launch_bounds__(256)
void rope_table_kernel() {
    int idx = blockIdx.x * blockDim.x + threadIdx.x;
    if (idx >= SEQ * 64) return;
    int i = idx & 63;
    int t = idx >> 6;
    float inv_freq = (float)exp(-log(10000.0) * ((double)i / 64.0));
    float ang_f = (float)t * inv_freq;
    double ang = (double)ang_f;
    g_rope_tab[idx] = make_float2((float)cos(ang), (float)sin(ang));
}

// ---------------------------------------------------------------------------
// RoPE + bf16 hi/lo split for q and k (fused)
// ---------------------------------------------------------------------------
__global__ __launch_bounds__(256)
void rope_split_kernel() {
    const size_t total = (size_t)BT * NHEAD * (HDIM / 2);
    size_t idx = (size_t)blockIdx.x * blockDim.x + threadIdx.x;
    if (idx >= total) return;

    int i  = (int)(idx & 63);
    int h  = (int)((idx >> 6) & (NHEAD - 1));
    int bt = (int)(idx >> 10);
    int t  = bt & (SEQ - 1);

    float2 cs = g_rope_tab[t * 64 + i];
    float c = cs.x, s = cs.y;

    size_t base = (size_t)bt * DMODEL + h * HDIM + i;

    float q1 = g_q[base], q2 = g_q[base + 64];
    float qa = q1 * c - q2 * s;
    float qb = q2 * c + q1 * s;
    __nv_bfloat16 qah = __float2bfloat16(qa);
    __nv_bfloat16 qbh = __float2bfloat16(qb);
    g_qhi[base]      = qah; g_qlo[base]      = __float2bfloat16(qa - __bfloat162float(qah));
    g_qhi[base + 64] = qbh; g_qlo[base + 64] = __float2bfloat16(qb - __bfloat162float(qbh));

    float k1 = g_k[base], k2 = g_k[base + 64];
    float ka = k1 * c - k2 * s;
    float kb = k2 * c + k1 * s;
    __nv_bfloat16 kah = __float2bfloat16(ka);
    __nv_bfloat16 kbh = __float2bfloat16(kb);
    g_khi[base]      = kah; g_klo[base]      = __float2bfloat16(ka - __bfloat162float(kah));
    g_khi[base + 64] = kbh; g_klo[base + 64] = __float2bfloat16(kb - __bfloat162float(kbh));
}

// ---------------------------------------------------------------------------
// bf16-split GEMM — 128-thread CTA, 4 warps (2x2 grid), 64x64 warp tile.
// 2 CTAs/SM. 2-stage pipeline. Ordering per iter (race-free):
//   sync                      -> all warps done reading buffer (kt-1)&1
//   prefetch kt+1 ; commit    -> writes buffer (kt+1)&1 == (kt-1)&1 (safe)
//   wait_group(1)             -> THIS thread's stage-kt group complete
//   sync                      -> ALL threads' stage-kt groups complete (publish)
//   MMAs on buffer kt&1
// (cp.async wait_group is per-thread; the post-wait barrier is mandatory
//  before reading rows another thread copied — R13 omitted it and raced.)
// ---------------------------------------------------------------------------
#define BM 128
#define BN 128
#define BK 32
#define ROWB 80
#define TILE_B (128 * ROWB)
#define STAGE_B (4 * TILE_B)          // 40960 B
#define GEMM_SMEM (2 * STAGE_B)       // 81920 B
#define GTHREADS 128

__device__ __forceinline__
void gemm_body(const __nv_bfloat16* __restrict__ Ahi,
               const __nv_bfloat16* __restrict__ Alo,
               const __nv_bfloat16* __restrict__ Bhi,
               const __nv_bfloat16* __restrict__ Blo,
               float* __restrict__ Cf,
               __nv_bfloat16* __restrict__ Chi,
               __nv_bfloat16* __restrict__ Clo,
               int N, int K, char* smem) {
    const uint32_t sb = smem_to_u32(smem);
    const int tid  = threadIdx.x;
    const int lane = tid & 31;
    const int wid  = tid >> 5;
    const int warp_m = wid & 1;     // 0..1  (64-row slab)
    const int warp_n = wid >> 1;    // 0..1  (64-col slab)

    const int row0 = blockIdx.y * BM;
    const int col0 = blockIdx.x * BN;

    float acc[4][8][4];
#pragma unroll
    for (int mi = 0; mi < 4; mi++)
#pragma unroll
        for (int ni = 0; ni < 8; ni++)
#pragma unroll
            for (int e = 0; e < 4; e++) acc[mi][ni][e] = 0.f;

    // Loader: 128 threads; per tile 128 rows x 4 chunks(16B); 4 rounds.
    const int r_ld  = tid >> 2;          // 0..31 (+32 per round)
    const int c_ld  = (tid & 3) * 16;
    const int ke_ld = (tid & 3) * 8;

    // ---- prologue: stage 0 ----
    {
#pragma unroll
        for (int rnd = 0; rnd < 4; rnd++) {
            int r = r_ld + rnd * 32;
            uint32_t d = sb + r * ROWB + c_ld;
            size_t ga = (size_t)(row0 + r) * K + ke_ld;
            size_t gb = (size_t)(col0 + r) * K + ke_ld;
            CP_ASYNC_16(d + 0 * TILE_B, Ahi + ga);
            CP_ASYNC_16(d + 1 * TILE_B, Alo + ga);
            CP_ASYNC_16(d + 2 * TILE_B, Bhi + gb);
            CP_ASYNC_16(d + 3 * TILE_B, Blo + gb);
        }
        CP_ASYNC_COMMIT();
    }

    const int niter = K / BK;
    for (int kt = 0; kt < niter; kt++) {
        __syncthreads();               // all warps done reading buffer (kt-1)&1

        // prefetch stage kt+1 into buffer (kt+1)&1 — overlaps with wait below
        if (kt + 1 < niter) {
            const int k0 = (kt + 1) * BK;
            const uint32_t base = sb + ((kt + 1) & 1) * STAGE_B;
#pragma unroll
            for (int rnd = 0; rnd < 4; rnd++) {
                int r = r_ld + rnd * 32;
                uint32_t d = base + r * ROWB + c_ld;
                size_t ga = (size_t)(row0 + r) * K + k0 + ke_ld;
                size_t gb = (size_t)(col0 + r) * K + k0 + ke_ld;
                CP_ASYNC_16(d + 0 * TILE_B, Ahi + ga);
                CP_ASYNC_16(d + 1 * TILE_B, Alo + ga);
                CP_ASYNC_16(d + 2 * TILE_B, Bhi + gb);
                CP_ASYNC_16(d + 3 * TILE_B, Blo + gb);
            }
        }
        CP_ASYNC_COMMIT();             // one group per iter (possibly empty)
        CP_ASYNC_WAIT_1();             // own stage-kt group complete
        __syncthreads();               // publish ALL threads' stage-kt data

        const uint32_t base  = sb + (kt & 1) * STAGE_B;
        const uint32_t a_hiB = base + 0 * TILE_B;
        const uint32_t a_loB = base + 1 * TILE_B;
        const uint32_t b_hiB = base + 2 * TILE_B;
        const uint32_t b_loB = base + 3 * TILE_B;

#pragma unroll
        for (int ks = 0; ks < 2; ks++) {
            const int kb = ks * 32;

            uint32_t ah[4][4], al[4][4], bh[8][2], bl[8][2];
            const int ar = warp_m * 64 + (lane & 15);
            const uint32_t acol = kb + ((lane >> 4) << 4);
#pragma unroll
            for (int mi = 0; mi < 4; mi++) {
                uint32_t off = (uint32_t)(ar + mi * 16) * ROWB + acol;
                LDMATRIX_X4(ah[mi][0], ah[mi][1], ah[mi][2], ah[mi][3], a_hiB + off);
                LDMATRIX_X4(al[mi][0], al[mi][1], al[mi][2], al[mi][3], a_loB + off);
            }
            const int brr = warp_n * 64 + ((lane >> 4) & 1) * 8 + (lane & 7);
            const uint32_t bcol = kb + ((lane >> 3) & 1) * 16;
#pragma unroll
            for (int nb = 0; nb < 4; nb++) {
                uint32_t off = (uint32_t)(brr + nb * 16) * ROWB + bcol;
                LDMATRIX_X4(bh[2*nb][0], bh[2*nb][1], bh[2*nb+1][0], bh[2*nb+1][1],
                            b_hiB + off);
                LDMATRIX_X4(bl[2*nb][0], bl[2*nb][1], bl[2*nb+1][0], bl[2*nb+1][1],
                            b_loB + off);
            }
#pragma unroll
            for (int mi = 0; mi < 4; mi++)
#pragma unroll
                for (int ni = 0; ni < 8; ni++) {
                    MMA_BF16(acc[mi][ni], ah[mi], bh[ni]);
                    MMA_BF16(acc[mi][ni], ah[mi], bl[ni]);
                    MMA_BF16(acc[mi][ni], al[mi], bh[ni]);
                }
        }
    }

    // ---- epilogue (no smem use) ----
#pragma unroll
    for (int mi = 0; mi < 4; mi++) {
        int r = row0 + warp_m * 64 + mi * 16 + (lane >> 2);
#pragma unroll
        for (int ni = 0; ni < 8; ni++) {
            int c = col0 + warp_n * 64 + ni * 8 + (lane & 3) * 2;
            if (Cf) {
                *(float2*)(Cf + (size_t)r * N + c) =
                    make_float2(acc[mi][ni][0], acc[mi][ni][1]);
                *(float2*)(Cf + (size_t)(r + 8) * N + c) =
                    make_float2(acc[mi][ni][2], acc[mi][ni][3]);
            } else {
#pragma unroll
                for (int rr = 0; rr < 2; rr++) {
                    float v0 = acc[mi][ni][rr*2], v1 = acc[mi][ni][rr*2+1];
                    __nv_bfloat162 ph, pl;
                    ph.x = __float2bfloat16(v0);
                    ph.y = __float2bfloat16(v1);
                    pl.x = __float2bfloat16(v0 - __bfloat162float(ph.x));
                    pl.y = __float2bfloat16(v1 - __bfloat162float(ph.y));
                    size_t off = (size_t)(r + rr * 8) * N + c;
                    *(__nv_bfloat162*)(Chi + off) = ph;
                    *(__nv_bfloat162*)(Clo + off) = pl;
                }
            }
        }
    }
}

// Q projection
__global__ __launch_bounds__(GTHREADS, 2)
void gemm_q() {
    extern __shared__ char smem[];
    gemm_body(g_xhi, g_xlo, g_wqhi, g_wqlo, g_q, nullptr, nullptr,
              DMODEL, DMODEL, smem);
}

// K+V projections (z: 0=K fp32, 1=V bf16 hi/lo)
__global__ __launch_bounds__(GTHREADS, 2)
void gemm_kv() {
    extern __shared__ char smem[];
    if (blockIdx.z == 0)
        gemm_body(g_xhi, g_xlo, g_wkhi, g_wklo, g_k, nullptr, nullptr,
                  DMODEL, DMODEL, smem);
    else
        gemm_body(g_xhi, g_xlo, g_wvhi, g_wvlo, nullptr, g_vhi, g_vlo,
                  DMODEL, DMODEL, smem);
}

// Output projection
__global__ __launch_bounds__(GTHREADS, 2)
void gemm_out(float* __restrict__ out) {
    extern __shared__ char smem[];
    gemm_body(g_ohi, g_olo, g_wohi, g_wolo, out, nullptr, nullptr,
              DMODEL, DMODEL, smem);
}

// ---------------------------------------------------------------------------
// Tensor-core flash attention (causal, bf16 hi/lo split, fp32 accum) — R10.
// ---------------------------------------------------------------------------
#define FROWB 272
#define FTILE (64 * FROWB)
#define SQH 0
#define SQL (1 * FTILE)
#define SKH (2 * FTILE)
#define SKL (3 * FTILE)
#define SVH (4 * FTILE)
#define SVL (5 * FTILE)
#define FA_SMEM (6 * FTILE)      // 104448 B

__global__ __launch_bounds__(128)
void flash_attn_tc() {
    extern __shared__ char sm[];
    const uint32_t sb = smem_to_u32(sm);
    const int tid  = threadIdx.x;
    const int lane = tid & 31;
    const int warp = tid >> 5;

    const int mb = (int)gridDim.x - 1 - (int)blockIdx.x;  // heavy tiles first
    const int bh = blockIdx.y;
    const int b  = bh >> 4;
    const int h  = bh & 15;
    const float scale = 0.08838834764831845f;

    const size_t hbase = (size_t)b * SEQ * DMODEL + (size_t)h * HDIM;

    {
        const size_t q0 = hbase + (size_t)mb * 64 * DMODEL;
        for (int i = tid; i < 1024; i += 128) {
            int r = i >> 4, c = i & 15;
            uint32_t d = sb + r * FROWB + c * 16;
            size_t g = q0 + (size_t)r * DMODEL + c * 8;
            CP_ASYNC_16(d + SQH, g_qhi + g);
            CP_ASYNC_16(d + SQL, g_qlo + g);
        }
        CP_ASYNC_COMMIT();
    }

    const int r0 = lane >> 2;
    float m0 = -INFINITY, m1 = -INFINITY, l0 = 0.f, l1 = 0.f;
    float oacc[16][4];
#pragma unroll
    for (int nb = 0; nb < 16; nb++)
#pragma unroll
        for (int e = 0; e < 4; e++) oacc[nb][e] = 0.f;

    for (int jb = 0; jb <= mb; jb++) {
        {
            const size_t kv0 = hbase + (size_t)jb * 64 * DMODEL;
            for (int i = tid; i < 1024; i += 128) {
                int r = i >> 4, c = i & 15;
                uint32_t d = sb + r * FROWB + c * 16;
                size_t g = kv0 + (size_t)r * DMODEL + c * 8;
                CP_ASYNC_16(d + SKH, g_khi + g);
                CP_ASYNC_16(d + SKL, g_klo + g);
                CP_ASYNC_16(d + SVH, g_vhi + g);
                CP_ASYNC_16(d + SVL, g_vlo + g);
            }
            CP_ASYNC_COMMIT();
            CP_ASYNC_WAIT_0();
            __syncthreads();
        }

        float sacc[8][4];
#pragma unroll
        for (int j = 0; j < 8; j++)
#pragma unroll
            for (int e = 0; e < 4; e++) sacc[j][e] = 0.f;

#pragma unroll
        for (int ks = 0; ks < 8; ks++) {
            const int kb = ks * 32;
            uint32_t aqh[4], aql[4];
            uint32_t aaddr = sb + (uint32_t)(warp * 16 + (lane & 15)) * FROWB
                           + kb + ((lane >> 4) << 4);
            LDMATRIX_X4(aqh[0], aqh[1], aqh[2], aqh[3], aaddr + SQH);
            LDMATRIX_X4(aql[0], aql[1], aql[2], aql[3], aaddr + SQL);
#pragma unroll
            for (int nsl = 0; nsl < 4; nsl++) {
                uint32_t bkh[2][2], bkl[2][2];
                uint32_t baddr = sb
                    + (uint32_t)(nsl * 16 + ((lane >> 4) & 1) * 8 + (lane & 7)) * FROWB
                    + kb + ((lane >> 3) & 1) * 16;
                LDMATRIX_X4(bkh[0][0], bkh[0][1], bkh[1][0], bkh[1][1], baddr + SKH);
                LDMATRIX_X4(bkl[0][0], bkl[0][1], bkl[1][0], bkl[1][1], baddr + SKL);
#pragma unroll
                for (int t = 0; t < 2; t++) {
                    int j = nsl * 2 + t;
                    MMA_BF16(sacc[j], aqh, bkh[t]);
                    MMA_BF16(sacc[j], aqh, bkl[t]);
                    MMA_BF16(sacc[j], aql, bkh[t]);
                }
            }
        }

#pragma unroll
        for (int j = 0; j < 8; j++)
#pragma unroll
            for (int e = 0; e < 4; e++) sacc[j][e] *= scale;

        if (jb == mb) {
            const int row0 = warp * 16 + r0;
            const int row1 = row0 + 8;
#pragma unroll
            for (int j = 0; j < 8; j++) {
                int c0 = j * 8 + (lane & 3) * 2;
                if (c0     > row0) sacc[j][0] = -INFINITY;
                if (c0 + 1 > row0) sacc[j][1] = -INFINITY;
                if (c0     > row1) sacc[j][2] = -INFINITY;
                if (c0 + 1 > row1) sacc[j][3] = -INFINITY;
            }
        }

        float mn0 = -INFINITY, mn1 = -INFINITY;
#pragma unroll
        for (int j = 0; j < 8; j++) {
            mn0 = fmaxf(mn0, fmaxf(sacc[j][0], sacc[j][1]));
            mn1 = fmaxf(mn1, fmaxf(sacc[j][2], sacc[j][3]));
        }
        mn0 = fmaxf(mn0, __shfl_xor_sync(0xffffffffu, mn0, 1));
        mn0 = fmaxf(mn0, __shfl_xor_sync(0xffffffffu, mn0, 2));
        mn1 = fmaxf(mn1, __shfl_xor_sync(0xffffffffu, mn1, 1));
        mn1 = fmaxf(mn1, __shfl_xor_sync(0xffffffffu, mn1, 2));
        mn0 = fmaxf(mn0, m0);
        mn1 = fmaxf(mn1, m1);

        float alpha0 = __expf(m0 - mn0);
        float alpha1 = __expf(m1 - mn1);
        m0 = mn0; m1 = mn1;
        l0 *= alpha0; l1 *= alpha1;
#pragma unroll
        for (int nb = 0; nb < 16; nb++) {
            oacc[nb][0] *= alpha0; oacc[nb][1] *= alpha0;
            oacc[nb][2] *= alpha1; oacc[nb][3] *= alpha1;
        }

        float rs0 = 0.f, rs1 = 0.f;
#pragma unroll
        for (int j = 0; j < 8; j++) {
            float p0 = __expf(sacc[j][0] - mn0);
            float p1 = __expf(sacc[j][1] - mn0);
            float p2 = __expf(sacc[j][2] - mn1);
            float p3 = __expf(sacc[j][3] - mn1);
            sacc[j][0] = p0; sacc[j][1] = p1; sacc[j][2] = p2; sacc[j][3] = p3;
            rs0 += p0 + p1; rs1 += p2 + p3;
        }
        rs0 += __shfl_xor_sync(0xffffffffu, rs0, 1);
        rs0 += __shfl_xor_sync(0xffffffffu, rs0, 2);
        rs1 += __shfl_xor_sync(0xffffffffu, rs1, 1);
        rs1 += __shfl_xor_sync(0xffffffffu, rs1, 2);
        l0 += rs0; l1 += rs1;

        uint32_t aph[4][4], apl[4][4];
#pragma unroll
        for (int kb2 = 0; kb2 < 4; kb2++) {
            int j = kb2 * 2;
#pragma unroll
            for (int q = 0; q < 4; q++) {
                int jj = j + (q >> 1);
                int e0 = (q & 1) * 2;
                float p0 = sacc[jj][e0], p1 = sacc[jj][e0 + 1];
                float h0 = __bfloat162float(__float2bfloat16(p0));
                float h1 = __bfloat162float(__float2bfloat16(p1));
                PACK_BF16X2(aph[kb2][q], h1, h0);
                PACK_BF16X2(apl[kb2][q], p1 - h1, p0 - h0);
            }
        }

#pragma unroll
        for (int kb2 = 0; kb2 < 4; kb2++) {
#pragma unroll
            for (int ns2 = 0; ns2 < 8; ns2++) {
                uint32_t bvh[2][2], bvl[2][2];
                uint32_t vaddr = sb
                    + (uint32_t)(kb2 * 16 + (lane & 7) + ((lane >> 3) & 1) * 8) * FROWB
                    + ns2 * 32 + ((lane >> 4) & 1) * 16;
                LDMATRIX_X4_TRANS(bvh[0][0], bvh[0][1], bvh[1][0], bvh[1][1], vaddr + SVH);
                LDMATRIX_X4_TRANS(bvl[0][0], bvl[0][1], bvl[1][0], bvl[1][1], vaddr + SVL);
#pragma unroll
                for (int t = 0; t < 2; t++) {
                    int nb = ns2 * 2 + t;
                    MMA_BF16(oacc[nb], aph[kb2], bvh[t]);
                    MMA_BF16(oacc[nb], apl[kb2], bvh[t]);
                    MMA_BF16(oacc[nb], aph[kb2], bvl[t]);
                }
            }
        }
        __syncthreads();
    }

    const float inv0 = 1.0f / l0;
    const float inv1 = 1.0f / l1;
    const size_t obase = hbase + (size_t)(mb * 64 + warp * 16) * DMODEL;
#pragma unroll
    for (int nb = 0; nb < 16; nb++) {
        int c = nb * 8 + (lane & 3) * 2;
#pragma unroll
        for (int rr = 0; rr < 2; rr++) {
            float v0 = oacc[nb][rr*2]     * (rr ? inv1 : inv0);
            float v1 = oacc[nb][rr*2 + 1] * (rr ? inv1 : inv0);
            __nv_bfloat162 ph, pl;
            ph.x = __float2bfloat16(v0);
            ph.y = __float2bfloat16(v1);
            pl.x = __float2bfloat16(v0 - __bfloat162float(ph.x));
            pl.y = __float2bfloat16(v1 - __bfloat162float(ph.y));
            size_t off = obase + (size_t)(r0 + rr * 8) * DMODEL + c;
            *(__nv_bfloat162*)(g_ohi + off) = ph;
            *(__nv_bfloat162*)(g_olo + off) = pl;
        }
    }
}

// ---------------------------------------------------------------------------
// Launch. Order: 1 x-split, 2 w-split(fused), 3 rope_table, 4 gemm_q,
//                5 gemm_kv (ncu target), 6 rope_split, 7 flash, 8 gemm_out.
// ---------------------------------------------------------------------------
extern "C" void kernel_launch(void* const* d_in, const int* in_sizes, int n_in,
                              void* d_out, int out_size) {
    const float* x  = (const float*)d_in[0];
    const float* wq = (const float*)d_in[1];
    const float* wk = (const float*)d_in[2];
    const float* wv = (const float*)d_in[3];
    const float* wo = (const float*)d_in[4];
    float* out = (float*)d_out;

    __nv_bfloat16 *xhi, *xlo;
    cudaGetSymbolAddress((void**)&xhi, g_xhi);
    cudaGetSymbolAddress((void**)&xlo, g_xlo);

    const size_t nx = (size_t)BT * DMODEL;        // 16.7M
    const size_t nw = (size_t)DMODEL * DMODEL;    // 4.19M

    // 1: x split   2: all weight splits (fused)
    split_bf16_v8<<<(int)(nx / 2048), 256>>>(x, xhi, xlo, nx);
    split_weights<<<dim3((unsigned)(nw / 2048), 4), 256>>>(wq, wk, wv, wo);

    // 3: RoPE table
    rope_table_kernel<<<(SEQ * 64 + 255) / 256, 256>>>();

    // 4: Q projection   5: K+V projections
    cudaFuncSetAttribute(gemm_q,
                         cudaFuncAttributeMaxDynamicSharedMemorySize, GEMM_SMEM);
    cudaFuncSetAttribute(gemm_kv,
                         cudaFuncAttributeMaxDynamicSharedMemorySize, GEMM_SMEM);
    gemm_q<<<dim3(DMODEL / BN, BT / BM, 1), GTHREADS, GEMM_SMEM>>>();
    gemm_kv<<<dim3(DMODEL / BN, BT / BM, 2), GTHREADS, GEMM_SMEM>>>();

    // 6: RoPE + q/k split
    {
        size_t total = (size_t)BT * NHEAD * (HDIM / 2);
        rope_split_kernel<<<(int)((total + 255) / 256), 256>>>();
    }

    // 7: tensor-core flash (writes ohi/olo directly)
    cudaFuncSetAttribute(flash_attn_tc,
                         cudaFuncAttributeMaxDynamicSharedMemorySize, FA_SMEM);
    flash_attn_tc<<<dim3(SEQ / 64, BATCH * NHEAD), 128, FA_SMEM>>>();

    // 8: output projection
    cudaFuncSetAttribute(gemm_out,
                         cudaFuncAttributeMaxDynamicSharedMemorySize, GEMM_SMEM);
    gemm_out<<<dim3(DMODEL / BN, BT / BM, 1), GTHREADS, GEMM_SMEM>>>(out);
}